// round 10
// baseline (speedup 1.0000x reference)
#include <cuda_runtime.h>
#include <cuda_fp16.h>
#include <cstdint>

#define N 8192
#define IN_F 512
#define OUT_F 64
#define NEG_SLOPE 0.01f
#define LOG2E 1.44269504088896340736f

#define TI 64
#define TJ 64
#define SPLIT 8
#define JSPAN (N / SPLIT)     // 1024
#define NT_S (JSPAN / TJ)     // 16

#define PSW 36   // Ps row stride (u32): frag banks conflict-free
#define VSW 36   // Vs row stride (u32)

// gat dynamic smem layout (bytes)
#define ADJ_OFF 0              // 2 x 16384 (adjacency tiles, 64x64 int)
#define VS_OFF  32768          // 2 x 9216  (V tiles, half2, n-major)
#define PS_OFF  51200          // 9216      (P tile, half2)
#define WH2_OFF 60416          // 2 x 256
#define WH1_OFF 60928          // 256
#define SHS_OFF 61184          // 256
#define RED_OFF 61440          // 4096
#define GAT_SMEM 65536

// Scratch (allocation-free rule: device globals)
__device__ __align__(16) float g_WH[N * OUT_F];
__device__ __align__(16) __half g_WHth[OUT_F * N];   // WH transposed, half
__device__ float g_wh1[N];           // pre-scaled by LOG2E
__device__ float g_wh2[N];           // pre-scaled by LOG2E
__device__ unsigned g_m2u = 0;       // order-preserving-key max of wh2L
__device__ __align__(16) float g_pacc[SPLIT * N * OUT_F];   // 16 MB partial PV
__device__ float g_psum[SPLIT * N];                         // partial row sums

__device__ __forceinline__ uint32_t su(const void* p) {
    return (uint32_t)__cvta_generic_to_shared(p);
}
#define CP_ASYNC16(dst, src) \
    asm volatile("cp.async.cg.shared.global [%0], [%1], 16;" :: "r"(dst), "l"(src))
#define CP_COMMIT() asm volatile("cp.async.commit_group;" ::: "memory")
#define CP_WAIT0()  asm volatile("cp.async.wait_group 0;" ::: "memory")

// order-preserving float<->unsigned key
__device__ __forceinline__ unsigned f2key(float x) {
    unsigned b = __float_as_uint(x);
    return (b & 0x80000000u) ? ~b : (b | 0x80000000u);
}
__device__ __forceinline__ float key2f(unsigned u) {
    return __uint_as_float((u & 0x80000000u) ? (u & 0x7FFFFFFFu) : ~u);
}
__device__ __forceinline__ uint32_t h2u(__half2 h) { return *(uint32_t*)&h; }

// f16 m16n8k16 tensor-core mma, f32 accumulate (baseline PTX, sm_103 ok)
__device__ __forceinline__ void mma_f16(float* c, uint32_t a0, uint32_t a1,
                                        uint32_t a2, uint32_t a3,
                                        uint32_t b0, uint32_t b1) {
    asm volatile(
        "mma.sync.aligned.m16n8k16.row.col.f32.f16.f16.f32 "
        "{%0,%1,%2,%3}, {%4,%5,%6,%7}, {%8,%9}, {%0,%1,%2,%3};"
        : "+f"(c[0]), "+f"(c[1]), "+f"(c[2]), "+f"(c[3])
        : "r"(a0), "r"(a1), "r"(a2), "r"(a3), "r"(b0), "r"(b1));
}

// ---------------------------------------------------------------------------
// Kernel A: WH = h @ W (+ transposed half copy + fused attn dots + wh2 max)
// 512 blocks x 256 threads; block tile 16 rows x 64 feats; thread 1x4.
// ---------------------------------------------------------------------------
#define HT 17
__global__ void __launch_bounds__(256) wh_kernel(const float* __restrict__ h,
                                                 const float* __restrict__ W,
                                                 const float* __restrict__ a) {
    __shared__ __align__(16) float Wc[64 * 64];   // Wc[k][f] 16 KB (reused as half stage)
    __shared__ float hT[64 * HT];                  // hT[k][row] 4.35 KB
    __shared__ float a1s[64], a2s[64];
    __shared__ float red1[16 * 17], red2[16 * 17];

    const int t  = threadIdx.x;
    const int tx = t & 15;       // feats tx*4 .. +3
    const int ty = t >> 4;       // row (0..15)
    const int r0 = blockIdx.x * 16;

    if (t < 64) { a1s[t] = a[t]; a2s[t] = a[OUT_F + t]; }

    unsigned long long acc0 = 0ull, acc1 = 0ull;

    for (int kc = 0; kc < IN_F; kc += 64) {
        __syncthreads();
#pragma unroll
        for (int i = 0; i < 4; i++) {            // Wc: 1024 float4, contiguous
            int idx = t + i * 256;
            ((float4*)Wc)[idx] = ((const float4*)W)[(size_t)(kc + (idx >> 4)) * 16 + (idx & 15)];
        }
        {   // hT: 16 rows x 64 k, coalesced read (lanes vary kq)
            int row = t >> 4, kq = t & 15;
            float4 hv = ((const float4*)h)[(size_t)(r0 + row) * (IN_F / 4) + (kc >> 2) + kq];
            hT[(kq * 4 + 0) * HT + row] = hv.x;
            hT[(kq * 4 + 1) * HT + row] = hv.y;
            hT[(kq * 4 + 2) * HT + row] = hv.z;
            hT[(kq * 4 + 3) * HT + row] = hv.w;
        }
        __syncthreads();
#pragma unroll 8
        for (int k = 0; k < 64; k++) {
            ulonglong2 w = *(const ulonglong2*)&Wc[k * 64 + tx * 4];
            float hb = hT[k * HT + ty];
            unsigned long long hd;
            asm("mov.b64 %0, {%1, %1};" : "=l"(hd) : "f"(hb));
            asm("fma.rn.f32x2 %0, %1, %2, %0;" : "+l"(acc0) : "l"(hd), "l"(w.x));
            asm("fma.rn.f32x2 %0, %1, %2, %0;" : "+l"(acc1) : "l"(hd), "l"(w.y));
        }
    }

    float v0, v1, v2, v3;
    asm("mov.b64 {%0, %1}, %2;" : "=f"(v0), "=f"(v1) : "l"(acc0));
    asm("mov.b64 {%0, %1}, %2;" : "=f"(v2), "=f"(v3) : "l"(acc1));
    *(float4*)(g_WH + (size_t)(r0 + ty) * OUT_F + tx * 4) = make_float4(v0, v1, v2, v3);

    // partial attn dots (registers only; smem writes after sync)
    float p1 = v0 * a1s[tx * 4] + v1 * a1s[tx * 4 + 1]
             + v2 * a1s[tx * 4 + 2] + v3 * a1s[tx * 4 + 3];
    float p2 = v0 * a2s[tx * 4] + v1 * a2s[tx * 4 + 1]
             + v2 * a2s[tx * 4 + 2] + v3 * a2s[tx * 4 + 3];

    __syncthreads();   // all threads done reading Wc/hT (loop) before reuse

    red1[ty * 17 + tx] = p1;
    red2[ty * 17 + tx] = p2;
    {   // half stage into Wc area: hs[f*18 + row]
        __half* hs = (__half*)Wc;
        hs[(tx * 4 + 0) * 18 + ty] = __float2half(v0);
        hs[(tx * 4 + 1) * 18 + ty] = __float2half(v1);
        hs[(tx * 4 + 2) * 18 + ty] = __float2half(v2);
        hs[(tx * 4 + 3) * 18 + ty] = __float2half(v3);
    }
    __syncthreads();

    if (t < 64) {   // coalesced-ish transposed store: 32B per feature
        const __half* hs = (const __half*)Wc;
        uint32_t u[8];
#pragma unroll
        for (int q = 0; q < 8; q++) u[q] = *(const uint32_t*)&hs[t * 18 + q * 2];
        uint4* dst = (uint4*)(g_WHth + (size_t)t * N + r0);
        dst[0] = make_uint4(u[0], u[1], u[2], u[3]);
        dst[1] = make_uint4(u[4], u[5], u[6], u[7]);
    }
    if (t < 16) {
        float d1 = 0.f, d2 = 0.f;
#pragma unroll
        for (int q = 0; q < 16; q++) { d1 += red1[t * 17 + q]; d2 += red2[t * 17 + q]; }
        d1 *= LOG2E; d2 *= LOG2E;
        g_wh1[r0 + t] = d1;
        g_wh2[r0 + t] = d2;
        float m = d2;
#pragma unroll
        for (int off = 8; off > 0; off >>= 1)
            m = fmaxf(m, __shfl_xor_sync(0x0000FFFFu, m, off));
        if (t == 0) atomicMax(&g_m2u, f2key(m));   // idempotent across replays
    }
}

// ---------------------------------------------------------------------------
// Kernel C: scores (SIMT, exp2, per-row shift) -> PV matmul (f16 m16n8k16)
//  grid (N/TI, SPLIT) = (128, 8). adjacency + V + wh2 via cp.async double buf.
// ---------------------------------------------------------------------------
__global__ void __launch_bounds__(256, 3) gat_kernel(const int* __restrict__ adj) {
    extern __shared__ __align__(16) char sm[];
    int*      adjs = (int*)(sm + ADJ_OFF);
    uint32_t* Vs   = (uint32_t*)(sm + VS_OFF);
    uint32_t* Ps   = (uint32_t*)(sm + PS_OFF);
    float*    wh2s = (float*)(sm + WH2_OFF);
    float*    wh1s = (float*)(sm + WH1_OFF);
    float*    shs  = (float*)(sm + SHS_OFF);
    float*    red  = (float*)(sm + RED_OFF);

    const int t    = threadIdx.x;
    const int ry   = t >> 4;            // score rows: ry + 16k
    const int tx   = t & 15;
    const int jb   = tx * 4;            // score cols within tile
    const int lane = t & 31;
    const int warp = t >> 5;
    const int gid  = lane >> 2;
    const int tid  = lane & 3;
    const int rs   = (warp >> 1) * 16;  // mma row stripe
    const int ch   = (warp & 1) * 32;   // mma col half
    const int i0   = blockIdx.x * TI;
    const int sp   = blockIdx.y;
    const int jbase = sp * JSPAN;

    const float m2L = key2f(g_m2u);
    if (t < TI) {
        float w1 = g_wh1[i0 + t];
        wh1s[t] = w1;
        float sh = w1 + m2L;
        shs[t] = (sh > 0.f) ? sh : NEG_SLOPE * sh;   // row max in log2 domain
    }

    // prologue group: adj(0), Vs(0), wh2(0)
#pragma unroll
    for (int i = 0; i < 4; i++) {
        int idx = t + i * 256;
        int row = idx >> 4, cc = idx & 15;
        CP_ASYNC16(su(sm + ADJ_OFF) + row * 256 + cc * 16,
                   (const void*)(adj + (size_t)(i0 + row) * N + jbase + cc * 4));
    }
#pragma unroll
    for (int i = 0; i < 2; i++) {
        int idx = t + i * 256;
        int f = idx >> 3, cc = idx & 7;
        CP_ASYNC16(su(sm + VS_OFF) + f * 144 + cc * 16,
                   (const void*)(g_WHth + (size_t)f * N + jbase + cc * 8));
    }
    if (t < 16) CP_ASYNC16(su(wh2s) + t * 16, (const void*)(g_wh2 + jbase + t * 4));
    CP_COMMIT();

    __syncthreads();   // wh1s/shs visible
    float b1r[4], shr[4];
#pragma unroll
    for (int k = 0; k < 4; k++) {
        b1r[k] = wh1s[ry + 16 * k];
        shr[k] = shs[ry + 16 * k];
    }

    float sums[4] = {0.f, 0.f, 0.f, 0.f};
    float c[4][4];
#pragma unroll
    for (int nt = 0; nt < 4; nt++)
#pragma unroll
        for (int q = 0; q < 4; q++) c[nt][q] = 0.f;

    for (int tt = 0; tt < NT_S; ++tt) {
        const int b = tt & 1;
        CP_WAIT0();
        __syncthreads();   // cp(tt) visible to all; mma(tt-1) complete

        // ---- issue cp for tile tt+1 into b^1 buffers (safe after sync) ----
        if (tt + 1 < NT_S) {
            const int jn = jbase + (tt + 1) * TJ;
            const int bo = (b ^ 1);
#pragma unroll
            for (int i = 0; i < 4; i++) {
                int idx = t + i * 256;
                int row = idx >> 4, cc = idx & 15;
                CP_ASYNC16(su(sm + ADJ_OFF) + bo * 16384 + row * 256 + cc * 16,
                           (const void*)(adj + (size_t)(i0 + row) * N + jn + cc * 4));
            }
#pragma unroll
            for (int i = 0; i < 2; i++) {
                int idx = t + i * 256;
                int f = idx >> 3, cc = idx & 7;
                CP_ASYNC16(su(sm + VS_OFF) + bo * 9216 + f * 144 + cc * 16,
                           (const void*)(g_WHth + (size_t)f * N + jn + cc * 8));
            }
            if (t < 16) CP_ASYNC16(su(wh2s) + bo * 256 + t * 16,
                                   (const void*)(g_wh2 + jn + t * 4));
        }
        CP_COMMIT();

        // ---- scores from smem adjacency -> Ps (half2), register row sums ----
        const float4 w2 = *(const float4*)&wh2s[b * 64 + jb];
        const int* ab = adjs + b * 4096;
#pragma unroll
        for (int k = 0; k < 4; k++) {
            const int r = ry + 16 * k;
            const int4 av = *(const int4*)(ab + r * 64 + jb);
            const float b1 = b1r[k];
            const float sh = shr[k];
            float e0 = b1 + w2.x; e0 = fmaxf(e0, NEG_SLOPE * e0) - sh;
            float e1 = b1 + w2.y; e1 = fmaxf(e1, NEG_SLOPE * e1) - sh;
            float e2 = b1 + w2.z; e2 = fmaxf(e2, NEG_SLOPE * e2) - sh;
            float e3 = b1 + w2.w; e3 = fmaxf(e3, NEG_SLOPE * e3) - sh;
            float p0 = (av.x > 0) ? exp2f(e0) : 0.f;
            float p1 = (av.y > 0) ? exp2f(e1) : 0.f;
            float p2 = (av.z > 0) ? exp2f(e2) : 0.f;
            float p3 = (av.w > 0) ? exp2f(e3) : 0.f;
            sums[k] += (p0 + p1) + (p2 + p3);
            __half2 h01 = __floats2half2_rn(p0, p1);
            __half2 h23 = __floats2half2_rn(p2, p3);
            *(uint2*)&Ps[r * PSW + tx * 2] = make_uint2(h2u(h01), h2u(h23));
        }
        __syncthreads();   // Ps complete

        // ---- tensor-core PV: per warp 16x32 output, k=64 in 4 k16 chunks ----
        const uint32_t* vb = Vs + b * 2304;
#pragma unroll
        for (int kc = 0; kc < 4; kc++) {
            const int k0 = kc * 8;
            uint32_t a0 = Ps[(rs + gid) * PSW + k0 + tid];
            uint32_t a1 = Ps[(rs + gid + 8) * PSW + k0 + tid];
            uint32_t a2 = Ps[(rs + gid) * PSW + k0 + tid + 4];
            uint32_t a3 = Ps[(rs + gid + 8) * PSW + k0 + tid + 4];
#pragma unroll
            for (int nt = 0; nt < 4; nt++) {
                const int n = ch + nt * 8 + gid;
                uint32_t b0 = vb[n * VSW + k0 + tid];
                uint32_t b1 = vb[n * VSW + k0 + tid + 4];
                mma_f16(c[nt], a0, a1, a2, a3, b0, b1);
            }
        }
    }

    __syncthreads();
    // ---- row-sum reduction -> g_psum ----
#pragma unroll
    for (int k = 0; k < 4; k++)
        red[(ry + 16 * k) * 16 + tx] = sums[k];
    __syncthreads();
    if (t < TI) {
        float s = 0.f;
#pragma unroll
        for (int q = 0; q < 16; q++) s += red[t * 16 + q];
        g_psum[sp * N + i0 + t] = s;
    }

    // ---- store unnormalized partials ----
#pragma unroll
    for (int nt = 0; nt < 4; nt++) {
        const int col = ch + nt * 8 + 2 * tid;
        const int row0 = i0 + rs + gid;
        *(float2*)&g_pacc[((size_t)sp * N + row0) * OUT_F + col] =
            make_float2(c[nt][0], c[nt][1]);
        *(float2*)&g_pacc[((size_t)sp * N + row0 + 8) * OUT_F + col] =
            make_float2(c[nt][2], c[nt][3]);
    }
}

// ---------------------------------------------------------------------------
// Kernel D: combine partials, normalize, elu
// ---------------------------------------------------------------------------
__global__ void __launch_bounds__(256) combine_kernel(float* __restrict__ out) {
    const int idx = blockIdx.x * 256 + threadIdx.x;   // N*16 float4 slots
    const int r = idx >> 4;

    float4 a = make_float4(0.f, 0.f, 0.f, 0.f);
    float s = 0.f;
#pragma unroll
    for (int sp = 0; sp < SPLIT; sp++) {
        float4 p = ((const float4*)g_pacc)[(size_t)sp * (N * 16) + idx];
        a.x += p.x; a.y += p.y; a.z += p.z; a.w += p.w;
        s += g_psum[sp * N + r];
    }
    const float inv = 1.f / s;
    float v;
    float4 o;
    v = a.x * inv; o.x = (v > 0.f) ? v : expm1f(v);
    v = a.y * inv; o.y = (v > 0.f) ? v : expm1f(v);
    v = a.z * inv; o.z = (v > 0.f) ? v : expm1f(v);
    v = a.w * inv; o.w = (v > 0.f) ? v : expm1f(v);
    ((float4*)out)[idx] = o;
}

// ---------------------------------------------------------------------------
extern "C" void kernel_launch(void* const* d_in, const int* in_sizes, int n_in,
                              void* d_out, int out_size) {
    const float* h   = nullptr;
    const int*   adj = nullptr;
    const float* W   = nullptr;
    const float* a   = nullptr;
    for (int i = 0; i < n_in; i++) {
        long long sz = in_sizes[i];
        if (sz == (long long)N * IN_F)          h   = (const float*)d_in[i];
        else if (sz == (long long)N * N)        adj = (const int*)d_in[i];
        else if (sz == (long long)IN_F * OUT_F) W   = (const float*)d_in[i];
        else if (sz == 2 * OUT_F)               a   = (const float*)d_in[i];
    }

    cudaFuncSetAttribute(gat_kernel, cudaFuncAttributeMaxDynamicSharedMemorySize, GAT_SMEM);

    wh_kernel<<<N / 16, 256>>>(h, W, a);
    gat_kernel<<<dim3(N / TI, SPLIT), 256, GAT_SMEM>>>(adj);
    combine_kernel<<<(N * 16) / 256, 256>>>((float*)d_out);
}

// round 11
// speedup vs baseline: 1.1313x; 1.1313x over previous
#include <cuda_runtime.h>
#include <cuda_fp16.h>
#include <cstdint>

#define N 8192
#define IN_F 512
#define OUT_F 64
#define NEG_SLOPE 0.01f
#define LOG2E 1.44269504088896340736f

#define TI 64
#define TJ 64
#define SPLIT 8
#define JSPAN (N / SPLIT)     // 1024
#define NT_S (JSPAN / TJ)     // 16

#define PSW 36   // Ps row stride (u32): frag banks conflict-free
#define VSW 36   // Vs row stride (u32)

// gat dynamic smem layout (bytes)
#define ADJ_OFF 0              // 2 x 16384 (adjacency tiles, 64x64 int)
#define VS_OFF  32768          // 2 x 9216  (V tiles, half2, n-major)
#define PS_OFF  51200          // 9216      (P tile, half2)
#define WH2_OFF 60416          // 2 x 256
#define WH1_OFF 60928          // 256
#define SHS_OFF 61184          // 256
#define RED_OFF 61440          // 4096
#define GAT_SMEM 65536

// Scratch (allocation-free rule: device globals)
__device__ __align__(16) float g_WH[N * OUT_F];
__device__ __align__(16) __half g_WHth[OUT_F * N];   // WH transposed, half
__device__ float g_wh1[N];           // pre-scaled by LOG2E
__device__ float g_wh2[N];           // pre-scaled by LOG2E
__device__ unsigned g_m2u = 0;       // order-preserving-key max of wh2L
__device__ __align__(16) float g_pacc[SPLIT * N * OUT_F];   // 16 MB partial PV
__device__ float g_psum[SPLIT * N];                         // partial row sums

__device__ __forceinline__ uint32_t su(const void* p) {
    return (uint32_t)__cvta_generic_to_shared(p);
}
#define CP_ASYNC16(dst, src) \
    asm volatile("cp.async.cg.shared.global [%0], [%1], 16;" :: "r"(dst), "l"(src))
#define CP_COMMIT() asm volatile("cp.async.commit_group;" ::: "memory")
#define CP_WAIT0()  asm volatile("cp.async.wait_group 0;" ::: "memory")

// order-preserving float<->unsigned key
__device__ __forceinline__ unsigned f2key(float x) {
    unsigned b = __float_as_uint(x);
    return (b & 0x80000000u) ? ~b : (b | 0x80000000u);
}
__device__ __forceinline__ float key2f(unsigned u) {
    return __uint_as_float((u & 0x80000000u) ? (u & 0x7FFFFFFFu) : ~u);
}
__device__ __forceinline__ uint32_t h2u(__half2 h) { return *(uint32_t*)&h; }

// f16 m16n8k16 tensor-core mma, f32 accumulate (baseline PTX, sm_103 ok)
__device__ __forceinline__ void mma_f16(float* c, uint32_t a0, uint32_t a1,
                                        uint32_t a2, uint32_t a3,
                                        uint32_t b0, uint32_t b1) {
    asm volatile(
        "mma.sync.aligned.m16n8k16.row.col.f32.f16.f16.f32 "
        "{%0,%1,%2,%3}, {%4,%5,%6,%7}, {%8,%9}, {%0,%1,%2,%3};"
        : "+f"(c[0]), "+f"(c[1]), "+f"(c[2]), "+f"(c[3])
        : "r"(a0), "r"(a1), "r"(a2), "r"(a3), "r"(b0), "r"(b1));
}

// ---------------------------------------------------------------------------
// Kernel A: WH = h @ W (+ transposed half copy + fused attn dots + wh2 max)
// 128 blocks x 256 threads; block tile 64 rows x 64 feats; thread 4x4 (R9
// structure: best measured LDS/MAC ratio); packed f32x2 accumulation.
// ---------------------------------------------------------------------------
#define HS 68
__global__ void __launch_bounds__(256) wh_kernel(const float* __restrict__ h,
                                                 const float* __restrict__ W,
                                                 const float* __restrict__ a) {
    __shared__ __align__(16) float Wc[64 * 64];   // Wc[k][f]    16 KB
    __shared__ __align__(16) float hT[64 * HS];   // hT[k][row]  17.4 KB
    __shared__ float a1s[64], a2s[64];
    __shared__ float red1[64 * 17], red2[64 * 17];  // 8.7 KB

    const int t  = threadIdx.x;
    const int tx = t & 15;       // feats tx*4 .. +3
    const int ty = t >> 4;       // rows  ty*4 .. +3
    const int r0 = blockIdx.x * 64;

    if (t < 64) { a1s[t] = a[t]; a2s[t] = a[OUT_F + t]; }

    unsigned long long acc[4][2];
#pragma unroll
    for (int r = 0; r < 4; r++) { acc[r][0] = 0ull; acc[r][1] = 0ull; }

    for (int kc = 0; kc < IN_F; kc += 64) {
        __syncthreads();
#pragma unroll
        for (int i = 0; i < 4; i++) {            // Wc: 1024 float4, contiguous
            int idx = t + i * 256;
            ((float4*)Wc)[idx] = ((const float4*)W)[(size_t)(kc + (idx >> 4)) * 16 + (idx & 15)];
        }
#pragma unroll
        for (int i = 0; i < 4; i++) {            // hT: transpose stage
            int idx = t + i * 256;
            int row = idx & 63, kq = idx >> 6;
            float4 hv = ((const float4*)h)[(size_t)(r0 + row) * (IN_F / 4) + (kc >> 2) + kq];
            hT[(kq * 4 + 0) * HS + row] = hv.x;
            hT[(kq * 4 + 1) * HS + row] = hv.y;
            hT[(kq * 4 + 2) * HS + row] = hv.z;
            hT[(kq * 4 + 3) * HS + row] = hv.w;
        }
        __syncthreads();
#pragma unroll 4
        for (int k = 0; k < 64; k++) {
            ulonglong2 w = *(const ulonglong2*)&Wc[k * 64 + tx * 4];
            float4 hv = *(const float4*)&hT[k * HS + ty * 4];
            unsigned long long hd;
            asm("mov.b64 %0, {%1, %1};" : "=l"(hd) : "f"(hv.x));
            asm("fma.rn.f32x2 %0, %1, %2, %0;" : "+l"(acc[0][0]) : "l"(hd), "l"(w.x));
            asm("fma.rn.f32x2 %0, %1, %2, %0;" : "+l"(acc[0][1]) : "l"(hd), "l"(w.y));
            asm("mov.b64 %0, {%1, %1};" : "=l"(hd) : "f"(hv.y));
            asm("fma.rn.f32x2 %0, %1, %2, %0;" : "+l"(acc[1][0]) : "l"(hd), "l"(w.x));
            asm("fma.rn.f32x2 %0, %1, %2, %0;" : "+l"(acc[1][1]) : "l"(hd), "l"(w.y));
            asm("mov.b64 %0, {%1, %1};" : "=l"(hd) : "f"(hv.z));
            asm("fma.rn.f32x2 %0, %1, %2, %0;" : "+l"(acc[2][0]) : "l"(hd), "l"(w.x));
            asm("fma.rn.f32x2 %0, %1, %2, %0;" : "+l"(acc[2][1]) : "l"(hd), "l"(w.y));
            asm("mov.b64 %0, {%1, %1};" : "=l"(hd) : "f"(hv.w));
            asm("fma.rn.f32x2 %0, %1, %2, %0;" : "+l"(acc[3][0]) : "l"(hd), "l"(w.x));
            asm("fma.rn.f32x2 %0, %1, %2, %0;" : "+l"(acc[3][1]) : "l"(hd), "l"(w.y));
        }
    }

    float vv[4][4];   // [r][q] = row ty*4+r, feat tx*4+q
#pragma unroll
    for (int r = 0; r < 4; r++) {
        asm("mov.b64 {%0, %1}, %2;" : "=f"(vv[r][0]), "=f"(vv[r][1]) : "l"(acc[r][0]));
        asm("mov.b64 {%0, %1}, %2;" : "=f"(vv[r][2]), "=f"(vv[r][3]) : "l"(acc[r][1]));
        *(float4*)(g_WH + (size_t)(r0 + ty * 4 + r) * OUT_F + tx * 4) =
            make_float4(vv[r][0], vv[r][1], vv[r][2], vv[r][3]);
    }
    // transposed half copy: g_WHth[f][row]
#pragma unroll
    for (int q = 0; q < 4; q++) {
        __half2 lo = __floats2half2_rn(vv[0][q], vv[1][q]);
        __half2 hi = __floats2half2_rn(vv[2][q], vv[3][q]);
        *(uint2*)(g_WHth + (size_t)(tx * 4 + q) * N + r0 + ty * 4) =
            make_uint2(h2u(lo), h2u(hi));
    }

    // fused attn dots: per-thread partials over feats tx*4..+3 for 4 rows
    __syncthreads();   // Wc/hT reads done; a1s/a2s visible
#pragma unroll
    for (int r = 0; r < 4; r++) {
        float p1 = vv[r][0] * a1s[tx * 4] + vv[r][1] * a1s[tx * 4 + 1]
                 + vv[r][2] * a1s[tx * 4 + 2] + vv[r][3] * a1s[tx * 4 + 3];
        float p2 = vv[r][0] * a2s[tx * 4] + vv[r][1] * a2s[tx * 4 + 1]
                 + vv[r][2] * a2s[tx * 4 + 2] + vv[r][3] * a2s[tx * 4 + 3];
        red1[(ty * 4 + r) * 17 + tx] = p1;
        red2[(ty * 4 + r) * 17 + tx] = p2;
    }
    __syncthreads();
    if (t < 64) {
        float d1 = 0.f, d2 = 0.f;
#pragma unroll
        for (int q = 0; q < 16; q++) { d1 += red1[t * 17 + q]; d2 += red2[t * 17 + q]; }
        d1 *= LOG2E; d2 *= LOG2E;
        g_wh1[r0 + t] = d1;
        g_wh2[r0 + t] = d2;
        float m = d2;
#pragma unroll
        for (int off = 16; off > 0; off >>= 1)
            m = fmaxf(m, __shfl_xor_sync(0xFFFFFFFFu, m, off));
        if ((t & 31) == 0) atomicMax(&g_m2u, f2key(m));   // idempotent across replays
    }
}

// ---------------------------------------------------------------------------
// Kernel C: scores (SIMT, exp2, per-row shift) -> PV matmul (f16 m16n8k16)
//  grid (N/TI, SPLIT) = (128, 8). adjacency + V + wh2 via cp.async double buf.
// ---------------------------------------------------------------------------
__global__ void __launch_bounds__(256, 3) gat_kernel(const int* __restrict__ adj) {
    extern __shared__ __align__(16) char sm[];
    int*      adjs = (int*)(sm + ADJ_OFF);
    uint32_t* Vs   = (uint32_t*)(sm + VS_OFF);
    uint32_t* Ps   = (uint32_t*)(sm + PS_OFF);
    float*    wh2s = (float*)(sm + WH2_OFF);
    float*    wh1s = (float*)(sm + WH1_OFF);
    float*    shs  = (float*)(sm + SHS_OFF);
    float*    red  = (float*)(sm + RED_OFF);

    const int t    = threadIdx.x;
    const int ry   = t >> 4;            // score rows: ry + 16k
    const int tx   = t & 15;
    const int jb   = tx * 4;            // score cols within tile
    const int lane = t & 31;
    const int warp = t >> 5;
    const int gid  = lane >> 2;
    const int tid  = lane & 3;
    const int rs   = (warp >> 1) * 16;  // mma row stripe
    const int ch   = (warp & 1) * 32;   // mma col half
    const int i0   = blockIdx.x * TI;
    const int sp   = blockIdx.y;
    const int jbase = sp * JSPAN;

    const float m2L = key2f(g_m2u);
    if (t < TI) {
        float w1 = g_wh1[i0 + t];
        wh1s[t] = w1;
        float sh = w1 + m2L;
        shs[t] = (sh > 0.f) ? sh : NEG_SLOPE * sh;   // row max in log2 domain
    }

    // prologue group: adj(0), Vs(0), wh2(0)
#pragma unroll
    for (int i = 0; i < 4; i++) {
        int idx = t + i * 256;
        int row = idx >> 4, cc = idx & 15;
        CP_ASYNC16(su(sm + ADJ_OFF) + row * 256 + cc * 16,
                   (const void*)(adj + (size_t)(i0 + row) * N + jbase + cc * 4));
    }
#pragma unroll
    for (int i = 0; i < 2; i++) {
        int idx = t + i * 256;
        int f = idx >> 3, cc = idx & 7;
        CP_ASYNC16(su(sm + VS_OFF) + f * 144 + cc * 16,
                   (const void*)(g_WHth + (size_t)f * N + jbase + cc * 8));
    }
    if (t < 16) CP_ASYNC16(su(wh2s) + t * 16, (const void*)(g_wh2 + jbase + t * 4));
    CP_COMMIT();

    __syncthreads();   // wh1s/shs visible
    float b1r[4], shr[4];
#pragma unroll
    for (int k = 0; k < 4; k++) {
        b1r[k] = wh1s[ry + 16 * k];
        shr[k] = shs[ry + 16 * k];
    }

    float sums[4] = {0.f, 0.f, 0.f, 0.f};
    float c[4][4];
#pragma unroll
    for (int nt = 0; nt < 4; nt++)
#pragma unroll
        for (int q = 0; q < 4; q++) c[nt][q] = 0.f;

    for (int tt = 0; tt < NT_S; ++tt) {
        const int b = tt & 1;
        CP_WAIT0();
        __syncthreads();   // cp(tt) visible to all; mma(tt-1) complete

        // ---- issue cp for tile tt+1 into b^1 buffers (safe after sync) ----
        if (tt + 1 < NT_S) {
            const int jn = jbase + (tt + 1) * TJ;
            const int bo = (b ^ 1);
#pragma unroll
            for (int i = 0; i < 4; i++) {
                int idx = t + i * 256;
                int row = idx >> 4, cc = idx & 15;
                CP_ASYNC16(su(sm + ADJ_OFF) + bo * 16384 + row * 256 + cc * 16,
                           (const void*)(adj + (size_t)(i0 + row) * N + jn + cc * 4));
            }
#pragma unroll
            for (int i = 0; i < 2; i++) {
                int idx = t + i * 256;
                int f = idx >> 3, cc = idx & 7;
                CP_ASYNC16(su(sm + VS_OFF) + bo * 9216 + f * 144 + cc * 16,
                           (const void*)(g_WHth + (size_t)f * N + jn + cc * 8));
            }
            if (t < 16) CP_ASYNC16(su(wh2s) + bo * 256 + t * 16,
                                   (const void*)(g_wh2 + jn + t * 4));
        }
        CP_COMMIT();

        // ---- scores from smem adjacency -> Ps (half2), register row sums ----
        const float4 w2 = *(const float4*)&wh2s[b * 64 + jb];
        const int* ab = adjs + b * 4096;
#pragma unroll
        for (int k = 0; k < 4; k++) {
            const int r = ry + 16 * k;
            const int4 av = *(const int4*)(ab + r * 64 + jb);
            const float b1 = b1r[k];
            const float sh = shr[k];
            float e0 = b1 + w2.x; e0 = fmaxf(e0, NEG_SLOPE * e0) - sh;
            float e1 = b1 + w2.y; e1 = fmaxf(e1, NEG_SLOPE * e1) - sh;
            float e2 = b1 + w2.z; e2 = fmaxf(e2, NEG_SLOPE * e2) - sh;
            float e3 = b1 + w2.w; e3 = fmaxf(e3, NEG_SLOPE * e3) - sh;
            float p0 = (av.x > 0) ? exp2f(e0) : 0.f;
            float p1 = (av.y > 0) ? exp2f(e1) : 0.f;
            float p2 = (av.z > 0) ? exp2f(e2) : 0.f;
            float p3 = (av.w > 0) ? exp2f(e3) : 0.f;
            sums[k] += (p0 + p1) + (p2 + p3);
            __half2 h01 = __floats2half2_rn(p0, p1);
            __half2 h23 = __floats2half2_rn(p2, p3);
            *(uint2*)&Ps[r * PSW + tx * 2] = make_uint2(h2u(h01), h2u(h23));
        }
        __syncthreads();   // Ps complete

        // ---- tensor-core PV: per warp 16x32 output, k=64 in 4 k16 chunks ----
        const uint32_t* vb = Vs + b * 2304;
#pragma unroll
        for (int kc = 0; kc < 4; kc++) {
            const int k0 = kc * 8;
            uint32_t a0 = Ps[(rs + gid) * PSW + k0 + tid];
            uint32_t a1 = Ps[(rs + gid + 8) * PSW + k0 + tid];
            uint32_t a2 = Ps[(rs + gid) * PSW + k0 + tid + 4];
            uint32_t a3 = Ps[(rs + gid + 8) * PSW + k0 + tid + 4];
#pragma unroll
            for (int nt = 0; nt < 4; nt++) {
                const int n = ch + nt * 8 + gid;
                uint32_t b0 = vb[n * VSW + k0 + tid];
                uint32_t b1 = vb[n * VSW + k0 + tid + 4];
                mma_f16(c[nt], a0, a1, a2, a3, b0, b1);
            }
        }
    }

    __syncthreads();
    // ---- row-sum reduction -> g_psum ----
#pragma unroll
    for (int k = 0; k < 4; k++)
        red[(ry + 16 * k) * 16 + tx] = sums[k];
    __syncthreads();
    if (t < TI) {
        float s = 0.f;
#pragma unroll
        for (int q = 0; q < 16; q++) s += red[t * 16 + q];
        g_psum[sp * N + i0 + t] = s;
    }

    // ---- store unnormalized partials ----
#pragma unroll
    for (int nt = 0; nt < 4; nt++) {
        const int col = ch + nt * 8 + 2 * tid;
        const int row0 = i0 + rs + gid;
        *(float2*)&g_pacc[((size_t)sp * N + row0) * OUT_F + col] =
            make_float2(c[nt][0], c[nt][1]);
        *(float2*)&g_pacc[((size_t)sp * N + row0 + 8) * OUT_F + col] =
            make_float2(c[nt][2], c[nt][3]);
    }
}

// ---------------------------------------------------------------------------
// Kernel D: combine partials, normalize, elu
// ---------------------------------------------------------------------------
__global__ void __launch_bounds__(256) combine_kernel(float* __restrict__ out) {
    const int idx = blockIdx.x * 256 + threadIdx.x;   // N*16 float4 slots
    const int r = idx >> 4;

    float4 a = make_float4(0.f, 0.f, 0.f, 0.f);
    float s = 0.f;
#pragma unroll
    for (int sp = 0; sp < SPLIT; sp++) {
        float4 p = ((const float4*)g_pacc)[(size_t)sp * (N * 16) + idx];
        a.x += p.x; a.y += p.y; a.z += p.z; a.w += p.w;
        s += g_psum[sp * N + r];
    }
    const float inv = 1.f / s;
    float v;
    float4 o;
    v = a.x * inv; o.x = (v > 0.f) ? v : expm1f(v);
    v = a.y * inv; o.y = (v > 0.f) ? v : expm1f(v);
    v = a.z * inv; o.z = (v > 0.f) ? v : expm1f(v);
    v = a.w * inv; o.w = (v > 0.f) ? v : expm1f(v);
    ((float4*)out)[idx] = o;
}

// ---------------------------------------------------------------------------
extern "C" void kernel_launch(void* const* d_in, const int* in_sizes, int n_in,
                              void* d_out, int out_size) {
    const float* h   = nullptr;
    const int*   adj = nullptr;
    const float* W   = nullptr;
    const float* a   = nullptr;
    for (int i = 0; i < n_in; i++) {
        long long sz = in_sizes[i];
        if (sz == (long long)N * IN_F)          h   = (const float*)d_in[i];
        else if (sz == (long long)N * N)        adj = (const int*)d_in[i];
        else if (sz == (long long)IN_F * OUT_F) W   = (const float*)d_in[i];
        else if (sz == 2 * OUT_F)               a   = (const float*)d_in[i];
    }

    cudaFuncSetAttribute(gat_kernel, cudaFuncAttributeMaxDynamicSharedMemorySize, GAT_SMEM);

    wh_kernel<<<N / 64, 256>>>(h, W, a);
    gat_kernel<<<dim3(N / TI, SPLIT), 256, GAT_SMEM>>>(adj);
    combine_kernel<<<(N * 16) / 256, 256>>>((float*)d_out);
}

// round 12
// speedup vs baseline: 1.2215x; 1.0797x over previous
#include <cuda_runtime.h>
#include <cuda_fp16.h>
#include <cstdint>

#define N 8192
#define IN_F 512
#define OUT_F 64
#define NEG_SLOPE 0.01f
#define LOG2E 1.44269504088896340736f

#define TI 64
#define TJ 64
#define SPLIT 8
#define JSPAN (N / SPLIT)     // 1024
#define NT_S (JSPAN / TJ)     // 16

#define PSW 36   // Ps row stride (u32): frag banks conflict-free
#define VSW 36   // Vs row stride (u32)

// gat dynamic smem layout (bytes)
#define ADJ_OFF 0              // 2 x 16384 (adjacency tiles, 64x64 int)
#define VS_OFF  32768          // 2 x 9216  (V tiles, half2, n-major)
#define PS_OFF  51200          // 9216      (P tile, half2)
#define WH2_OFF 60416          // 2 x 256
#define WH1_OFF 60928          // 256
#define SHS_OFF 61184          // 256
#define RED_OFF 61440          // 4096
#define GAT_SMEM 65536

// Scratch (allocation-free rule: device globals)
__device__ __align__(16) float g_WHp[2 * N * OUT_F];   // K-split partials (4 MB)
__device__ __align__(16) __half g_WHth[OUT_F * N];     // WH transposed, half
__device__ float g_wh1[N];           // pre-scaled by LOG2E
__device__ float g_wh2[N];           // pre-scaled by LOG2E
__device__ unsigned g_m2u = 0;       // order-preserving-key max of wh2L
__device__ __align__(16) float g_pacc[SPLIT * N * OUT_F];   // 16 MB partial PV
__device__ float g_psum[SPLIT * N];                         // partial row sums

__device__ __forceinline__ uint32_t su(const void* p) {
    return (uint32_t)__cvta_generic_to_shared(p);
}
#define CP_ASYNC16(dst, src) \
    asm volatile("cp.async.cg.shared.global [%0], [%1], 16;" :: "r"(dst), "l"(src))
#define CP_COMMIT() asm volatile("cp.async.commit_group;" ::: "memory")
#define CP_WAIT0()  asm volatile("cp.async.wait_group 0;" ::: "memory")

// order-preserving float<->unsigned key
__device__ __forceinline__ unsigned f2key(float x) {
    unsigned b = __float_as_uint(x);
    return (b & 0x80000000u) ? ~b : (b | 0x80000000u);
}
__device__ __forceinline__ float key2f(unsigned u) {
    return __uint_as_float((u & 0x80000000u) ? (u & 0x7FFFFFFFu) : ~u);
}
__device__ __forceinline__ uint32_t h2u(__half2 h) { return *(uint32_t*)&h; }

// f16 m16n8k16 tensor-core mma, f32 accumulate (baseline PTX, sm_103 ok)
__device__ __forceinline__ void mma_f16(float* c, uint32_t a0, uint32_t a1,
                                        uint32_t a2, uint32_t a3,
                                        uint32_t b0, uint32_t b1) {
    asm volatile(
        "mma.sync.aligned.m16n8k16.row.col.f32.f16.f16.f32 "
        "{%0,%1,%2,%3}, {%4,%5,%6,%7}, {%8,%9}, {%0,%1,%2,%3};"
        : "+f"(c[0]), "+f"(c[1]), "+f"(c[2]), "+f"(c[3])
        : "r"(a0), "r"(a1), "r"(a2), "r"(a3), "r"(b0), "r"(b1));
}

// ---------------------------------------------------------------------------
// Kernel A1: wh_main — partial WH over a K-half.
// grid (128, 2) x 256 threads; block tile 64 rows x 64 feats x 256 K;
// thread 4x4; packed f32x2; next chunk register-prefetched during compute.
// ---------------------------------------------------------------------------
#define HS 68
__global__ void __launch_bounds__(256) wh_main(const float* __restrict__ h,
                                               const float* __restrict__ W) {
    __shared__ __align__(16) float Wc[64 * 64];   // Wc[k][f]    16 KB
    __shared__ __align__(16) float hT[64 * HS];   // hT[k][row]  17.4 KB

    const int t  = threadIdx.x;
    const int tx = t & 15;       // feats tx*4 .. +3
    const int ty = t >> 4;       // rows  ty*4 .. +3
    const int r0 = blockIdx.x * 64;
    const int kbase = blockIdx.y * 256;   // K-half origin

    float4 wr[4], hr[4];
#pragma unroll
    for (int i = 0; i < 4; i++) {        // prologue: chunk 0 into regs
        int idx = t + i * 256;
        wr[i] = ((const float4*)W)[(size_t)(kbase + (idx >> 4)) * 16 + (idx & 15)];
        hr[i] = ((const float4*)h)[(size_t)(r0 + (idx & 63)) * (IN_F / 4)
                                   + (kbase >> 2) + (idx >> 6)];
    }

    unsigned long long acc[4][2];
#pragma unroll
    for (int r = 0; r < 4; r++) { acc[r][0] = 0ull; acc[r][1] = 0ull; }

    for (int c = 0; c < 4; c++) {
        __syncthreads();                  // previous chunk's reads done
#pragma unroll
        for (int i = 0; i < 4; i++) {     // stage regs -> smem
            int idx = t + i * 256;
            ((float4*)Wc)[idx] = wr[i];
            int row = idx & 63, kq = idx >> 6;
            hT[(kq * 4 + 0) * HS + row] = hr[i].x;
            hT[(kq * 4 + 1) * HS + row] = hr[i].y;
            hT[(kq * 4 + 2) * HS + row] = hr[i].z;
            hT[(kq * 4 + 3) * HS + row] = hr[i].w;
        }
        __syncthreads();
        if (c < 3) {                      // prefetch next chunk into regs
#pragma unroll
            for (int i = 0; i < 4; i++) {
                int idx = t + i * 256;
                wr[i] = ((const float4*)W)[(size_t)(kbase + (c + 1) * 64 + (idx >> 4)) * 16
                                           + (idx & 15)];
                hr[i] = ((const float4*)h)[(size_t)(r0 + (idx & 63)) * (IN_F / 4)
                                           + (kbase >> 2) + (c + 1) * 16 + (idx >> 6)];
            }
        }
#pragma unroll 4
        for (int k = 0; k < 64; k++) {
            ulonglong2 w = *(const ulonglong2*)&Wc[k * 64 + tx * 4];
            float4 hv = *(const float4*)&hT[k * HS + ty * 4];
            unsigned long long hd;
            asm("mov.b64 %0, {%1, %1};" : "=l"(hd) : "f"(hv.x));
            asm("fma.rn.f32x2 %0, %1, %2, %0;" : "+l"(acc[0][0]) : "l"(hd), "l"(w.x));
            asm("fma.rn.f32x2 %0, %1, %2, %0;" : "+l"(acc[0][1]) : "l"(hd), "l"(w.y));
            asm("mov.b64 %0, {%1, %1};" : "=l"(hd) : "f"(hv.y));
            asm("fma.rn.f32x2 %0, %1, %2, %0;" : "+l"(acc[1][0]) : "l"(hd), "l"(w.x));
            asm("fma.rn.f32x2 %0, %1, %2, %0;" : "+l"(acc[1][1]) : "l"(hd), "l"(w.y));
            asm("mov.b64 %0, {%1, %1};" : "=l"(hd) : "f"(hv.z));
            asm("fma.rn.f32x2 %0, %1, %2, %0;" : "+l"(acc[2][0]) : "l"(hd), "l"(w.x));
            asm("fma.rn.f32x2 %0, %1, %2, %0;" : "+l"(acc[2][1]) : "l"(hd), "l"(w.y));
            asm("mov.b64 %0, {%1, %1};" : "=l"(hd) : "f"(hv.w));
            asm("fma.rn.f32x2 %0, %1, %2, %0;" : "+l"(acc[3][0]) : "l"(hd), "l"(w.x));
            asm("fma.rn.f32x2 %0, %1, %2, %0;" : "+l"(acc[3][1]) : "l"(hd), "l"(w.y));
        }
    }

    float* dst = g_WHp + (size_t)blockIdx.y * (N * OUT_F);
#pragma unroll
    for (int r = 0; r < 4; r++) {
        float v0, v1, v2, v3;
        asm("mov.b64 {%0, %1}, %2;" : "=f"(v0), "=f"(v1) : "l"(acc[r][0]));
        asm("mov.b64 {%0, %1}, %2;" : "=f"(v2), "=f"(v3) : "l"(acc[r][1]));
        *(float4*)(dst + (size_t)(r0 + ty * 4 + r) * OUT_F + tx * 4) =
            make_float4(v0, v1, v2, v3);
    }
}

// ---------------------------------------------------------------------------
// Kernel A2: wh_epi — combine K-halves, emit half-transposed WH, attn dots,
// wh2 max. grid 512 x 256 (16 rows/block).
// ---------------------------------------------------------------------------
__global__ void __launch_bounds__(256) wh_epi(const float* __restrict__ a) {
    __shared__ float a1s[64], a2s[64];
    __shared__ float red1[16 * 17], red2[16 * 17];
    __shared__ __half hs[64 * 18];

    const int t   = threadIdx.x;
    const int fq  = t & 15;      // feats fq*4 .. +3
    const int row = t >> 4;      // 0..15
    const int r0  = blockIdx.x * 16;

    if (t < 64) { a1s[t] = a[t]; a2s[t] = a[OUT_F + t]; }

    const size_t idx = (size_t)(r0 + row) * 16 + fq;
    float4 va = ((const float4*)g_WHp)[idx];
    float4 vb = ((const float4*)g_WHp)[(size_t)N * 16 + idx];
    float v0 = va.x + vb.x, v1 = va.y + vb.y, v2 = va.z + vb.z, v3 = va.w + vb.w;

    hs[(fq * 4 + 0) * 18 + row] = __float2half(v0);
    hs[(fq * 4 + 1) * 18 + row] = __float2half(v1);
    hs[(fq * 4 + 2) * 18 + row] = __float2half(v2);
    hs[(fq * 4 + 3) * 18 + row] = __float2half(v3);
    __syncthreads();   // a1s/a2s visible

    float p1 = v0 * a1s[fq * 4] + v1 * a1s[fq * 4 + 1]
             + v2 * a1s[fq * 4 + 2] + v3 * a1s[fq * 4 + 3];
    float p2 = v0 * a2s[fq * 4] + v1 * a2s[fq * 4 + 1]
             + v2 * a2s[fq * 4 + 2] + v3 * a2s[fq * 4 + 3];
    red1[row * 17 + fq] = p1;
    red2[row * 17 + fq] = p2;
    __syncthreads();

    if (t < 64) {   // transposed half store: 32B per feature
        uint32_t u[8];
#pragma unroll
        for (int q = 0; q < 8; q++) u[q] = *(const uint32_t*)&hs[t * 18 + q * 2];
        uint4* dst = (uint4*)(g_WHth + (size_t)t * N + r0);
        dst[0] = make_uint4(u[0], u[1], u[2], u[3]);
        dst[1] = make_uint4(u[4], u[5], u[6], u[7]);
    }
    if (t < 16) {
        float d1 = 0.f, d2 = 0.f;
#pragma unroll
        for (int q = 0; q < 16; q++) { d1 += red1[t * 17 + q]; d2 += red2[t * 17 + q]; }
        d1 *= LOG2E; d2 *= LOG2E;
        g_wh1[r0 + t] = d1;
        g_wh2[r0 + t] = d2;
        float m = d2;
#pragma unroll
        for (int off = 8; off > 0; off >>= 1)
            m = fmaxf(m, __shfl_xor_sync(0x0000FFFFu, m, off));
        if (t == 0) atomicMax(&g_m2u, f2key(m));   // idempotent across replays
    }
}

// ---------------------------------------------------------------------------
// Kernel C: scores (SIMT, exp2, per-row shift) -> PV matmul (f16 m16n8k16)
//  grid (N/TI, SPLIT) = (128, 8). adjacency + V + wh2 via cp.async double buf.
// ---------------------------------------------------------------------------
__global__ void __launch_bounds__(256, 3) gat_kernel(const int* __restrict__ adj) {
    extern __shared__ __align__(16) char sm[];
    int*      adjs = (int*)(sm + ADJ_OFF);
    uint32_t* Vs   = (uint32_t*)(sm + VS_OFF);
    uint32_t* Ps   = (uint32_t*)(sm + PS_OFF);
    float*    wh2s = (float*)(sm + WH2_OFF);
    float*    wh1s = (float*)(sm + WH1_OFF);
    float*    shs  = (float*)(sm + SHS_OFF);
    float*    red  = (float*)(sm + RED_OFF);

    const int t    = threadIdx.x;
    const int ry   = t >> 4;            // score rows: ry + 16k
    const int tx   = t & 15;
    const int jb   = tx * 4;            // score cols within tile
    const int lane = t & 31;
    const int warp = t >> 5;
    const int gid  = lane >> 2;
    const int tid  = lane & 3;
    const int rs   = (warp >> 1) * 16;  // mma row stripe
    const int ch   = (warp & 1) * 32;   // mma col half
    const int i0   = blockIdx.x * TI;
    const int sp   = blockIdx.y;
    const int jbase = sp * JSPAN;

    const float m2L = key2f(g_m2u);
    if (t < TI) {
        float w1 = g_wh1[i0 + t];
        wh1s[t] = w1;
        float sh = w1 + m2L;
        shs[t] = (sh > 0.f) ? sh : NEG_SLOPE * sh;   // row max in log2 domain
    }

    // prologue group: adj(0), Vs(0), wh2(0)
#pragma unroll
    for (int i = 0; i < 4; i++) {
        int idx = t + i * 256;
        int row = idx >> 4, cc = idx & 15;
        CP_ASYNC16(su(sm + ADJ_OFF) + row * 256 + cc * 16,
                   (const void*)(adj + (size_t)(i0 + row) * N + jbase + cc * 4));
    }
#pragma unroll
    for (int i = 0; i < 2; i++) {
        int idx = t + i * 256;
        int f = idx >> 3, cc = idx & 7;
        CP_ASYNC16(su(sm + VS_OFF) + f * 144 + cc * 16,
                   (const void*)(g_WHth + (size_t)f * N + jbase + cc * 8));
    }
    if (t < 16) CP_ASYNC16(su(wh2s) + t * 16, (const void*)(g_wh2 + jbase + t * 4));
    CP_COMMIT();

    __syncthreads();   // wh1s/shs visible
    float b1r[4], shr[4];
#pragma unroll
    for (int k = 0; k < 4; k++) {
        b1r[k] = wh1s[ry + 16 * k];
        shr[k] = shs[ry + 16 * k];
    }

    float sums[4] = {0.f, 0.f, 0.f, 0.f};
    float c[4][4];
#pragma unroll
    for (int nt = 0; nt < 4; nt++)
#pragma unroll
        for (int q = 0; q < 4; q++) c[nt][q] = 0.f;

    for (int tt = 0; tt < NT_S; ++tt) {
        const int b = tt & 1;
        CP_WAIT0();
        __syncthreads();   // cp(tt) visible to all; mma(tt-1) complete

        // ---- issue cp for tile tt+1 into b^1 buffers (safe after sync) ----
        if (tt + 1 < NT_S) {
            const int jn = jbase + (tt + 1) * TJ;
            const int bo = (b ^ 1);
#pragma unroll
            for (int i = 0; i < 4; i++) {
                int idx = t + i * 256;
                int row = idx >> 4, cc = idx & 15;
                CP_ASYNC16(su(sm + ADJ_OFF) + bo * 16384 + row * 256 + cc * 16,
                           (const void*)(adj + (size_t)(i0 + row) * N + jn + cc * 4));
            }
#pragma unroll
            for (int i = 0; i < 2; i++) {
                int idx = t + i * 256;
                int f = idx >> 3, cc = idx & 7;
                CP_ASYNC16(su(sm + VS_OFF) + bo * 9216 + f * 144 + cc * 16,
                           (const void*)(g_WHth + (size_t)f * N + jn + cc * 8));
            }
            if (t < 16) CP_ASYNC16(su(wh2s) + bo * 256 + t * 16,
                                   (const void*)(g_wh2 + jn + t * 4));
        }
        CP_COMMIT();

        // ---- scores from smem adjacency -> Ps (half2), register row sums ----
        const float4 w2 = *(const float4*)&wh2s[b * 64 + jb];
        const int* ab = adjs + b * 4096;
#pragma unroll
        for (int k = 0; k < 4; k++) {
            const int r = ry + 16 * k;
            const int4 av = *(const int4*)(ab + r * 64 + jb);
            const float b1 = b1r[k];
            const float sh = shr[k];
            float e0 = b1 + w2.x; e0 = fmaxf(e0, NEG_SLOPE * e0) - sh;
            float e1 = b1 + w2.y; e1 = fmaxf(e1, NEG_SLOPE * e1) - sh;
            float e2 = b1 + w2.z; e2 = fmaxf(e2, NEG_SLOPE * e2) - sh;
            float e3 = b1 + w2.w; e3 = fmaxf(e3, NEG_SLOPE * e3) - sh;
            float p0 = (av.x > 0) ? exp2f(e0) : 0.f;
            float p1 = (av.y > 0) ? exp2f(e1) : 0.f;
            float p2 = (av.z > 0) ? exp2f(e2) : 0.f;
            float p3 = (av.w > 0) ? exp2f(e3) : 0.f;
            sums[k] += (p0 + p1) + (p2 + p3);
            __half2 h01 = __floats2half2_rn(p0, p1);
            __half2 h23 = __floats2half2_rn(p2, p3);
            *(uint2*)&Ps[r * PSW + tx * 2] = make_uint2(h2u(h01), h2u(h23));
        }
        __syncthreads();   // Ps complete

        // ---- tensor-core PV: per warp 16x32 output, k=64 in 4 k16 chunks ----
        const uint32_t* vb = Vs + b * 2304;
#pragma unroll
        for (int kc = 0; kc < 4; kc++) {
            const int k0 = kc * 8;
            uint32_t a0 = Ps[(rs + gid) * PSW + k0 + tid];
            uint32_t a1 = Ps[(rs + gid + 8) * PSW + k0 + tid];
            uint32_t a2 = Ps[(rs + gid) * PSW + k0 + tid + 4];
            uint32_t a3 = Ps[(rs + gid + 8) * PSW + k0 + tid + 4];
#pragma unroll
            for (int nt = 0; nt < 4; nt++) {
                const int n = ch + nt * 8 + gid;
                uint32_t b0 = vb[n * VSW + k0 + tid];
                uint32_t b1 = vb[n * VSW + k0 + tid + 4];
                mma_f16(c[nt], a0, a1, a2, a3, b0, b1);
            }
        }
    }

    __syncthreads();
    // ---- row-sum reduction -> g_psum ----
#pragma unroll
    for (int k = 0; k < 4; k++)
        red[(ry + 16 * k) * 16 + tx] = sums[k];
    __syncthreads();
    if (t < TI) {
        float s = 0.f;
#pragma unroll
        for (int q = 0; q < 16; q++) s += red[t * 16 + q];
        g_psum[sp * N + i0 + t] = s;
    }

    // ---- store unnormalized partials ----
#pragma unroll
    for (int nt = 0; nt < 4; nt++) {
        const int col = ch + nt * 8 + 2 * tid;
        const int row0 = i0 + rs + gid;
        *(float2*)&g_pacc[((size_t)sp * N + row0) * OUT_F + col] =
            make_float2(c[nt][0], c[nt][1]);
        *(float2*)&g_pacc[((size_t)sp * N + row0 + 8) * OUT_F + col] =
            make_float2(c[nt][2], c[nt][3]);
    }
}

// ---------------------------------------------------------------------------
// Kernel D: combine partials, normalize, elu
// ---------------------------------------------------------------------------
__global__ void __launch_bounds__(256) combine_kernel(float* __restrict__ out) {
    const int idx = blockIdx.x * 256 + threadIdx.x;   // N*16 float4 slots
    const int r = idx >> 4;

    float4 a = make_float4(0.f, 0.f, 0.f, 0.f);
    float s = 0.f;
#pragma unroll
    for (int sp = 0; sp < SPLIT; sp++) {
        float4 p = ((const float4*)g_pacc)[(size_t)sp * (N * 16) + idx];
        a.x += p.x; a.y += p.y; a.z += p.z; a.w += p.w;
        s += g_psum[sp * N + r];
    }
    const float inv = 1.f / s;
    float v;
    float4 o;
    v = a.x * inv; o.x = (v > 0.f) ? v : expm1f(v);
    v = a.y * inv; o.y = (v > 0.f) ? v : expm1f(v);
    v = a.z * inv; o.z = (v > 0.f) ? v : expm1f(v);
    v = a.w * inv; o.w = (v > 0.f) ? v : expm1f(v);
    ((float4*)out)[idx] = o;
}

// ---------------------------------------------------------------------------
extern "C" void kernel_launch(void* const* d_in, const int* in_sizes, int n_in,
                              void* d_out, int out_size) {
    const float* h   = nullptr;
    const int*   adj = nullptr;
    const float* W   = nullptr;
    const float* a   = nullptr;
    for (int i = 0; i < n_in; i++) {
        long long sz = in_sizes[i];
        if (sz == (long long)N * IN_F)          h   = (const float*)d_in[i];
        else if (sz == (long long)N * N)        adj = (const int*)d_in[i];
        else if (sz == (long long)IN_F * OUT_F) W   = (const float*)d_in[i];
        else if (sz == 2 * OUT_F)               a   = (const float*)d_in[i];
    }

    cudaFuncSetAttribute(gat_kernel, cudaFuncAttributeMaxDynamicSharedMemorySize, GAT_SMEM);

    wh_main<<<dim3(128, 2), 256>>>(h, W);
    wh_epi<<<512, 256>>>(a);
    gat_kernel<<<dim3(N / TI, SPLIT), 256, GAT_SMEM>>>(adj);
    combine_kernel<<<(N * 16) / 256, 256>>>((float*)d_out);
}

// round 13
// speedup vs baseline: 1.4191x; 1.1618x over previous
#include <cuda_runtime.h>
#include <cuda_fp16.h>
#include <cstdint>

#define N 8192
#define IN_F 512
#define OUT_F 64
#define NEG_SLOPE 0.01f
#define LOG2E 1.44269504088896340736f

#define TI 64
#define TJ 64
#define SPLIT 16
#define JSPAN (N / SPLIT)     // 512
#define NT_S (JSPAN / TJ)     // 8

#define PSW 36   // Ps row stride (u32): frag banks conflict-free
#define VSW 36   // Vs row stride (u32)
#define VBUF (72 * VSW)       // V buffer stride (u32): 64 data rows + 8 ones/zero rows

// gat dynamic smem layout (bytes)
#define ADJ_OFF 0              // 2 x 16384 (adjacency tiles, 64x64 int)
#define VS_OFF  32768          // 2 x 10368 (V tiles + ones rows, half2, n-major)
#define PS_OFF  53504          // 9216      (P tile, half2)
#define WH2_OFF 62720          // 2 x 256
#define WH1_OFF 63232          // 256
#define SHS_OFF 63488          // 256
#define GAT_SMEM 63744

// Scratch (allocation-free rule: device globals)
__device__ __align__(16) float g_WHp[2 * N * OUT_F];   // K-split partials (4 MB)
__device__ __align__(16) __half g_WHth[OUT_F * N];     // WH transposed, half
__device__ float g_wh1[N];           // pre-scaled by LOG2E
__device__ float g_wh2[N];           // pre-scaled by LOG2E
__device__ unsigned g_m2u = 0;       // order-preserving-key max of wh2L
__device__ __align__(16) float g_pacc[SPLIT * N * OUT_F];   // 32 MB partial PV
__device__ float g_psum[SPLIT * N];                         // partial row sums

__device__ __forceinline__ uint32_t su(const void* p) {
    return (uint32_t)__cvta_generic_to_shared(p);
}
#define CP_ASYNC16(dst, src) \
    asm volatile("cp.async.cg.shared.global [%0], [%1], 16;" :: "r"(dst), "l"(src))
#define CP_COMMIT() asm volatile("cp.async.commit_group;" ::: "memory")
#define CP_WAIT0()  asm volatile("cp.async.wait_group 0;" ::: "memory")

// order-preserving float<->unsigned key
__device__ __forceinline__ unsigned f2key(float x) {
    unsigned b = __float_as_uint(x);
    return (b & 0x80000000u) ? ~b : (b | 0x80000000u);
}
__device__ __forceinline__ float key2f(unsigned u) {
    return __uint_as_float((u & 0x80000000u) ? (u & 0x7FFFFFFFu) : ~u);
}
__device__ __forceinline__ uint32_t h2u(__half2 h) { return *(uint32_t*)&h; }

// f16 m16n8k16 tensor-core mma, f32 accumulate (baseline PTX, sm_103 ok)
__device__ __forceinline__ void mma_f16(float* c, uint32_t a0, uint32_t a1,
                                        uint32_t a2, uint32_t a3,
                                        uint32_t b0, uint32_t b1) {
    asm volatile(
        "mma.sync.aligned.m16n8k16.row.col.f32.f16.f16.f32 "
        "{%0,%1,%2,%3}, {%4,%5,%6,%7}, {%8,%9}, {%0,%1,%2,%3};"
        : "+f"(c[0]), "+f"(c[1]), "+f"(c[2]), "+f"(c[3])
        : "r"(a0), "r"(a1), "r"(a2), "r"(a3), "r"(b0), "r"(b1));
}

// ---------------------------------------------------------------------------
// Kernel A1: wh_main — partial WH over a K-half.
// grid (128, 2) x 256 threads; block tile 64 rows x 64 feats x 256 K;
// thread 4x4; packed f32x2; next chunk register-prefetched during compute.
// ---------------------------------------------------------------------------
#define HS 68
__global__ void __launch_bounds__(256) wh_main(const float* __restrict__ h,
                                               const float* __restrict__ W) {
    __shared__ __align__(16) float Wc[64 * 64];   // Wc[k][f]    16 KB
    __shared__ __align__(16) float hT[64 * HS];   // hT[k][row]  17.4 KB

    const int t  = threadIdx.x;
    const int tx = t & 15;       // feats tx*4 .. +3
    const int ty = t >> 4;       // rows  ty*4 .. +3
    const int r0 = blockIdx.x * 64;
    const int kbase = blockIdx.y * 256;   // K-half origin

    float4 wr[4], hr[4];
#pragma unroll
    for (int i = 0; i < 4; i++) {        // prologue: chunk 0 into regs
        int idx = t + i * 256;
        wr[i] = ((const float4*)W)[(size_t)(kbase + (idx >> 4)) * 16 + (idx & 15)];
        hr[i] = ((const float4*)h)[(size_t)(r0 + (idx & 63)) * (IN_F / 4)
                                   + (kbase >> 2) + (idx >> 6)];
    }

    unsigned long long acc[4][2];
#pragma unroll
    for (int r = 0; r < 4; r++) { acc[r][0] = 0ull; acc[r][1] = 0ull; }

    for (int c = 0; c < 4; c++) {
        __syncthreads();                  // previous chunk's reads done
#pragma unroll
        for (int i = 0; i < 4; i++) {     // stage regs -> smem
            int idx = t + i * 256;
            ((float4*)Wc)[idx] = wr[i];
            int row = idx & 63, kq = idx >> 6;
            hT[(kq * 4 + 0) * HS + row] = hr[i].x;
            hT[(kq * 4 + 1) * HS + row] = hr[i].y;
            hT[(kq * 4 + 2) * HS + row] = hr[i].z;
            hT[(kq * 4 + 3) * HS + row] = hr[i].w;
        }
        __syncthreads();
        if (c < 3) {                      // prefetch next chunk into regs
#pragma unroll
            for (int i = 0; i < 4; i++) {
                int idx = t + i * 256;
                wr[i] = ((const float4*)W)[(size_t)(kbase + (c + 1) * 64 + (idx >> 4)) * 16
                                           + (idx & 15)];
                hr[i] = ((const float4*)h)[(size_t)(r0 + (idx & 63)) * (IN_F / 4)
                                           + (kbase >> 2) + (c + 1) * 16 + (idx >> 6)];
            }
        }
#pragma unroll 4
        for (int k = 0; k < 64; k++) {
            ulonglong2 w = *(const ulonglong2*)&Wc[k * 64 + tx * 4];
            float4 hv = *(const float4*)&hT[k * HS + ty * 4];
            unsigned long long hd;
            asm("mov.b64 %0, {%1, %1};" : "=l"(hd) : "f"(hv.x));
            asm("fma.rn.f32x2 %0, %1, %2, %0;" : "+l"(acc[0][0]) : "l"(hd), "l"(w.x));
            asm("fma.rn.f32x2 %0, %1, %2, %0;" : "+l"(acc[0][1]) : "l"(hd), "l"(w.y));
            asm("mov.b64 %0, {%1, %1};" : "=l"(hd) : "f"(hv.y));
            asm("fma.rn.f32x2 %0, %1, %2, %0;" : "+l"(acc[1][0]) : "l"(hd), "l"(w.x));
            asm("fma.rn.f32x2 %0, %1, %2, %0;" : "+l"(acc[1][1]) : "l"(hd), "l"(w.y));
            asm("mov.b64 %0, {%1, %1};" : "=l"(hd) : "f"(hv.z));
            asm("fma.rn.f32x2 %0, %1, %2, %0;" : "+l"(acc[2][0]) : "l"(hd), "l"(w.x));
            asm("fma.rn.f32x2 %0, %1, %2, %0;" : "+l"(acc[2][1]) : "l"(hd), "l"(w.y));
            asm("mov.b64 %0, {%1, %1};" : "=l"(hd) : "f"(hv.w));
            asm("fma.rn.f32x2 %0, %1, %2, %0;" : "+l"(acc[3][0]) : "l"(hd), "l"(w.x));
            asm("fma.rn.f32x2 %0, %1, %2, %0;" : "+l"(acc[3][1]) : "l"(hd), "l"(w.y));
        }
    }

    float* dst = g_WHp + (size_t)blockIdx.y * (N * OUT_F);
#pragma unroll
    for (int r = 0; r < 4; r++) {
        float v0, v1, v2, v3;
        asm("mov.b64 {%0, %1}, %2;" : "=f"(v0), "=f"(v1) : "l"(acc[r][0]));
        asm("mov.b64 {%0, %1}, %2;" : "=f"(v2), "=f"(v3) : "l"(acc[r][1]));
        *(float4*)(dst + (size_t)(r0 + ty * 4 + r) * OUT_F + tx * 4) =
            make_float4(v0, v1, v2, v3);
    }
}

// ---------------------------------------------------------------------------
// Kernel A2: wh_epi — combine K-halves, emit half-transposed WH, attn dots,
// wh2 max. grid 512 x 256 (16 rows/block).
// ---------------------------------------------------------------------------
__global__ void __launch_bounds__(256) wh_epi(const float* __restrict__ a) {
    __shared__ float a1s[64], a2s[64];
    __shared__ float red1[16 * 17], red2[16 * 17];
    __shared__ __half hs[64 * 18];

    const int t   = threadIdx.x;
    const int fq  = t & 15;      // feats fq*4 .. +3
    const int row = t >> 4;      // 0..15
    const int r0  = blockIdx.x * 16;

    if (t < 64) { a1s[t] = a[t]; a2s[t] = a[OUT_F + t]; }

    const size_t idx = (size_t)(r0 + row) * 16 + fq;
    float4 va = ((const float4*)g_WHp)[idx];
    float4 vb = ((const float4*)g_WHp)[(size_t)N * 16 + idx];
    float v0 = va.x + vb.x, v1 = va.y + vb.y, v2 = va.z + vb.z, v3 = va.w + vb.w;

    hs[(fq * 4 + 0) * 18 + row] = __float2half(v0);
    hs[(fq * 4 + 1) * 18 + row] = __float2half(v1);
    hs[(fq * 4 + 2) * 18 + row] = __float2half(v2);
    hs[(fq * 4 + 3) * 18 + row] = __float2half(v3);
    __syncthreads();   // a1s/a2s visible

    float p1 = v0 * a1s[fq * 4] + v1 * a1s[fq * 4 + 1]
             + v2 * a1s[fq * 4 + 2] + v3 * a1s[fq * 4 + 3];
    float p2 = v0 * a2s[fq * 4] + v1 * a2s[fq * 4 + 1]
             + v2 * a2s[fq * 4 + 2] + v3 * a2s[fq * 4 + 3];
    red1[row * 17 + fq] = p1;
    red2[row * 17 + fq] = p2;
    __syncthreads();

    if (t < 64) {   // transposed half store: 32B per feature
        uint32_t u[8];
#pragma unroll
        for (int q = 0; q < 8; q++) u[q] = *(const uint32_t*)&hs[t * 18 + q * 2];
        uint4* dst = (uint4*)(g_WHth + (size_t)t * N + r0);
        dst[0] = make_uint4(u[0], u[1], u[2], u[3]);
        dst[1] = make_uint4(u[4], u[5], u[6], u[7]);
    }
    if (t < 16) {
        float d1 = 0.f, d2 = 0.f;
#pragma unroll
        for (int q = 0; q < 16; q++) { d1 += red1[t * 17 + q]; d2 += red2[t * 17 + q]; }
        d1 *= LOG2E; d2 *= LOG2E;
        g_wh1[r0 + t] = d1;
        g_wh2[r0 + t] = d2;
        float m = d2;
#pragma unroll
        for (int off = 8; off > 0; off >>= 1)
            m = fmaxf(m, __shfl_xor_sync(0x0000FFFFu, m, off));
        if (t == 0) atomicMax(&g_m2u, f2key(m));   // idempotent across replays
    }
}

// ---------------------------------------------------------------------------
// Kernel C: scores (exp2 in half2, per-row shift, mask folded into shift)
//  -> PV matmul (f16 m16n8k16); row sums via ones-column mma (ch==0 warps).
//  grid (N/TI, SPLIT) = (128, 16). adjacency + V + wh2 via cp.async double buf.
// ---------------------------------------------------------------------------
__global__ void __launch_bounds__(256, 3) gat_kernel(const int* __restrict__ adj) {
    extern __shared__ __align__(16) char sm[];
    int*      adjs = (int*)(sm + ADJ_OFF);
    uint32_t* Vs   = (uint32_t*)(sm + VS_OFF);
    uint32_t* Ps   = (uint32_t*)(sm + PS_OFF);
    float*    wh2s = (float*)(sm + WH2_OFF);
    float*    wh1s = (float*)(sm + WH1_OFF);
    float*    shs  = (float*)(sm + SHS_OFF);

    const int t    = threadIdx.x;
    const int ry   = t >> 4;            // score rows: ry + 16k
    const int tx   = t & 15;
    const int jb   = tx * 4;            // score cols within tile
    const int lane = t & 31;
    const int warp = t >> 5;
    const int gid  = lane >> 2;
    const int tid  = lane & 3;
    const int rs   = (warp >> 1) * 16;  // mma row stripe
    const int ch   = (warp & 1) * 32;   // mma col half
    const int i0   = blockIdx.x * TI;
    const int sp   = blockIdx.y;
    const int jbase = sp * JSPAN;

    const float m2L = key2f(g_m2u);
    if (t < TI) {
        float w1 = g_wh1[i0 + t];
        wh1s[t] = w1;
        float sh = w1 + m2L;
        shs[t] = (sh > 0.f) ? sh : NEG_SLOPE * sh;   // row max in log2 domain
    }

    // prologue group: adj(0), Vs(0), wh2(0)
#pragma unroll
    for (int i = 0; i < 4; i++) {
        int idx = t + i * 256;
        int row = idx >> 4, cc = idx & 15;
        CP_ASYNC16(su(sm + ADJ_OFF) + row * 256 + cc * 16,
                   (const void*)(adj + (size_t)(i0 + row) * N + jbase + cc * 4));
    }
#pragma unroll
    for (int i = 0; i < 2; i++) {
        int idx = t + i * 256;
        int f = idx >> 3, cc = idx & 7;
        CP_ASYNC16(su(sm + VS_OFF) + f * 144 + cc * 16,
                   (const void*)(g_WHth + (size_t)f * N + jbase + cc * 8));
    }
    if (t < 16) CP_ASYNC16(su(wh2s) + t * 16, (const void*)(g_wh2 + jbase + t * 4));
    CP_COMMIT();

    // init ones/zero rows (64..71) of both V buffers (cp only writes rows 0..63)
    for (int w = t; w < 2 * 8 * VSW; w += 256) {
        int buf = w / (8 * VSW);
        int rem = w % (8 * VSW);
        int rr  = 64 + rem / VSW;
        Vs[buf * VBUF + rr * VSW + rem % VSW] = (rr == 64) ? 0x3C003C00u : 0u;
    }

    __syncthreads();   // wh1s/shs + ones rows visible
    float b1r[4], mshr[4];
#pragma unroll
    for (int k = 0; k < 4; k++) {
        b1r[k]  = wh1s[ry + 16 * k];
        mshr[k] = -shs[ry + 16 * k];
    }

    float c[4][4], csum[4];
#pragma unroll
    for (int nt = 0; nt < 4; nt++)
#pragma unroll
        for (int q = 0; q < 4; q++) c[nt][q] = 0.f;
#pragma unroll
    for (int q = 0; q < 4; q++) csum[q] = 0.f;

    for (int tt = 0; tt < NT_S; ++tt) {
        const int b = tt & 1;
        CP_WAIT0();
        __syncthreads();   // cp(tt) visible to all; mma(tt-1) complete

        // ---- issue cp for tile tt+1 into b^1 buffers (safe after sync) ----
        if (tt + 1 < NT_S) {
            const int jn = jbase + (tt + 1) * TJ;
            const int bo = (b ^ 1);
#pragma unroll
            for (int i = 0; i < 4; i++) {
                int idx = t + i * 256;
                int row = idx >> 4, cc = idx & 15;
                CP_ASYNC16(su(sm + ADJ_OFF) + bo * 16384 + row * 256 + cc * 16,
                           (const void*)(adj + (size_t)(i0 + row) * N + jn + cc * 4));
            }
#pragma unroll
            for (int i = 0; i < 2; i++) {
                int idx = t + i * 256;
                int f = idx >> 3, cc = idx & 7;
                CP_ASYNC16(su(sm + VS_OFF) + bo * 10368 + f * 144 + cc * 16,
                           (const void*)(g_WHth + (size_t)f * N + jn + cc * 8));
            }
            if (t < 16) CP_ASYNC16(su(wh2s) + bo * 256 + t * 16,
                                   (const void*)(g_wh2 + jn + t * 4));
        }
        CP_COMMIT();

        // ---- scores: e in fp32, mask via shift-select, exp in half2 ----
        const float4 w2 = *(const float4*)&wh2s[b * 64 + jb];
        const int* ab = adjs + b * 4096;
#pragma unroll
        for (int k = 0; k < 4; k++) {
            const int r = ry + 16 * k;
            const int4 av = *(const int4*)(ab + r * 64 + jb);
            const float b1 = b1r[k];
            const float ms = mshr[k];
            const float mB = ms - 1024.0f;   // masked: exp2 underflows to 0 in half
            float x0 = b1 + w2.x; x0 = fmaxf(x0, NEG_SLOPE * x0) + ((av.x > 0) ? ms : mB);
            float x1 = b1 + w2.y; x1 = fmaxf(x1, NEG_SLOPE * x1) + ((av.y > 0) ? ms : mB);
            float x2 = b1 + w2.z; x2 = fmaxf(x2, NEG_SLOPE * x2) + ((av.z > 0) ? ms : mB);
            float x3 = b1 + w2.w; x3 = fmaxf(x3, NEG_SLOPE * x3) + ((av.w > 0) ? ms : mB);
            uint32_t e01 = h2u(__floats2half2_rn(x0, x1));
            uint32_t e23 = h2u(__floats2half2_rn(x2, x3));
            uint32_t p01, p23;
            asm("ex2.approx.f16x2 %0, %1;" : "=r"(p01) : "r"(e01));
            asm("ex2.approx.f16x2 %0, %1;" : "=r"(p23) : "r"(e23));
            *(uint2*)&Ps[r * PSW + tx * 2] = make_uint2(p01, p23);
        }
        __syncthreads();   // Ps complete

        // ---- tensor-core PV: per warp 16x32 output + ones-column row sums ----
        const uint32_t* vb = Vs + b * VBUF;
#pragma unroll
        for (int kc = 0; kc < 4; kc++) {
            const int k0 = kc * 8;
            uint32_t a0 = Ps[(rs + gid) * PSW + k0 + tid];
            uint32_t a1 = Ps[(rs + gid + 8) * PSW + k0 + tid];
            uint32_t a2 = Ps[(rs + gid) * PSW + k0 + tid + 4];
            uint32_t a3 = Ps[(rs + gid + 8) * PSW + k0 + tid + 4];
#pragma unroll
            for (int nt = 0; nt < 4; nt++) {
                const int n = ch + nt * 8 + gid;
                uint32_t b0 = vb[n * VSW + k0 + tid];
                uint32_t b1v = vb[n * VSW + k0 + tid + 4];
                mma_f16(c[nt], a0, a1, a2, a3, b0, b1v);
            }
            if (ch == 0) {   // ones-column: row sums in fp32 accumulator
                uint32_t b0 = vb[(64 + gid) * VSW + k0 + tid];
                uint32_t b1v = vb[(64 + gid) * VSW + k0 + tid + 4];
                mma_f16(csum, a0, a1, a2, a3, b0, b1v);
            }
        }
    }

    // ---- row sums from ones-column accumulators ----
    if (ch == 0 && tid == 0) {
        g_psum[sp * N + i0 + rs + gid]     = csum[0];
        g_psum[sp * N + i0 + rs + gid + 8] = csum[2];
    }

    // ---- store unnormalized partials ----
#pragma unroll
    for (int nt = 0; nt < 4; nt++) {
        const int col = ch + nt * 8 + 2 * tid;
        const int row0 = i0 + rs + gid;
        *(float2*)&g_pacc[((size_t)sp * N + row0) * OUT_F + col] =
            make_float2(c[nt][0], c[nt][1]);
        *(float2*)&g_pacc[((size_t)sp * N + row0 + 8) * OUT_F + col] =
            make_float2(c[nt][2], c[nt][3]);
    }
}

// ---------------------------------------------------------------------------
// Kernel D: combine partials, normalize, elu
// ---------------------------------------------------------------------------
__global__ void __launch_bounds__(256) combine_kernel(float* __restrict__ out) {
    const int idx = blockIdx.x * 256 + threadIdx.x;   // N*16 float4 slots
    const int r = idx >> 4;

    float4 a = make_float4(0.f, 0.f, 0.f, 0.f);
    float s = 0.f;
#pragma unroll
    for (int sp = 0; sp < SPLIT; sp++) {
        float4 p = ((const float4*)g_pacc)[(size_t)sp * (N * 16) + idx];
        a.x += p.x; a.y += p.y; a.z += p.z; a.w += p.w;
        s += g_psum[sp * N + r];
    }
    const float inv = 1.f / s;
    float v;
    float4 o;
    v = a.x * inv; o.x = (v > 0.f) ? v : expm1f(v);
    v = a.y * inv; o.y = (v > 0.f) ? v : expm1f(v);
    v = a.z * inv; o.z = (v > 0.f) ? v : expm1f(v);
    v = a.w * inv; o.w = (v > 0.f) ? v : expm1f(v);
    ((float4*)out)[idx] = o;
}

// ---------------------------------------------------------------------------
extern "C" void kernel_launch(void* const* d_in, const int* in_sizes, int n_in,
                              void* d_out, int out_size) {
    const float* h   = nullptr;
    const int*   adj = nullptr;
    const float* W   = nullptr;
    const float* a   = nullptr;
    for (int i = 0; i < n_in; i++) {
        long long sz = in_sizes[i];
        if (sz == (long long)N * IN_F)          h   = (const float*)d_in[i];
        else if (sz == (long long)N * N)        adj = (const int*)d_in[i];
        else if (sz == (long long)IN_F * OUT_F) W   = (const float*)d_in[i];
        else if (sz == 2 * OUT_F)               a   = (const float*)d_in[i];
    }

    cudaFuncSetAttribute(gat_kernel, cudaFuncAttributeMaxDynamicSharedMemorySize, GAT_SMEM);

    wh_main<<<dim3(128, 2), 256>>>(h, W);
    wh_epi<<<512, 256>>>(a);
    gat_kernel<<<dim3(N / TI, SPLIT), 256, GAT_SMEM>>>(adj);
    combine_kernel<<<(N * 16) / 256, 256>>>((float*)d_out);
}

// round 14
// speedup vs baseline: 1.4485x; 1.0207x over previous
#include <cuda_runtime.h>
#include <cuda_fp16.h>
#include <cstdint>

#define N 8192
#define IN_F 512
#define OUT_F 64
#define NEG_SLOPE 0.01f
#define LOG2E 1.44269504088896340736f

#define TI 64
#define TJ 64
#define SPLIT 16
#define JSPAN (N / SPLIT)     // 512
#define NT_S (JSPAN / TJ)     // 8

#define PSW 36   // Ps row stride (u32): frag banks conflict-free
#define VSW 36   // Vs row stride (u32)
#define VBUF (72 * VSW)       // V buffer stride (u32): 64 data rows + 8 ones/zero rows

// gat dynamic smem layout (bytes)
#define ADJ_OFF 0              // 2 x 16384 (adjacency tiles, 64x64 int)
#define VS_OFF  32768          // 2 x 10368 (V tiles + ones rows, half2, n-major)
#define PS_OFF  53504          // 9216      (P tile, half2)
#define WH2_OFF 62720          // 2 x 256
#define WH1_OFF 63232          // 256
#define SHS_OFF 63488          // 256
#define GAT_SMEM 63744

// Scratch (allocation-free rule: device globals)
#define KSPL 4
__device__ __align__(16) float g_WHp[KSPL * N * OUT_F];   // K-split partials (8 MB)
__device__ __align__(16) __half g_WHth[OUT_F * N];        // WH transposed, half
__device__ float g_wh1[N];           // pre-scaled by LOG2E
__device__ float g_wh2[N];           // pre-scaled by LOG2E
__device__ unsigned g_m2u = 0;       // order-preserving-key max of wh2L
__device__ __align__(16) __half g_pacc[SPLIT * N * OUT_F];  // 16 MB partial PV (half)
__device__ float g_psum[SPLIT * N];                         // partial row sums

__device__ __forceinline__ uint32_t su(const void* p) {
    return (uint32_t)__cvta_generic_to_shared(p);
}
#define CP_ASYNC16(dst, src) \
    asm volatile("cp.async.cg.shared.global [%0], [%1], 16;" :: "r"(dst), "l"(src))
#define CP_COMMIT() asm volatile("cp.async.commit_group;" ::: "memory")
#define CP_WAIT0()  asm volatile("cp.async.wait_group 0;" ::: "memory")

// order-preserving float<->unsigned key
__device__ __forceinline__ unsigned f2key(float x) {
    unsigned b = __float_as_uint(x);
    return (b & 0x80000000u) ? ~b : (b | 0x80000000u);
}
__device__ __forceinline__ float key2f(unsigned u) {
    return __uint_as_float((u & 0x80000000u) ? (u & 0x7FFFFFFFu) : ~u);
}
__device__ __forceinline__ uint32_t h2u(__half2 h) { return *(uint32_t*)&h; }

// f16 m16n8k16 tensor-core mma, f32 accumulate (baseline PTX, sm_103 ok)
__device__ __forceinline__ void mma_f16(float* c, uint32_t a0, uint32_t a1,
                                        uint32_t a2, uint32_t a3,
                                        uint32_t b0, uint32_t b1) {
    asm volatile(
        "mma.sync.aligned.m16n8k16.row.col.f32.f16.f16.f32 "
        "{%0,%1,%2,%3}, {%4,%5,%6,%7}, {%8,%9}, {%0,%1,%2,%3};"
        : "+f"(c[0]), "+f"(c[1]), "+f"(c[2]), "+f"(c[3])
        : "r"(a0), "r"(a1), "r"(a2), "r"(a3), "r"(b0), "r"(b1));
}

// ---------------------------------------------------------------------------
// Kernel A1: wh_main — partial WH over a K-quarter.
// grid (128, 4) x 256 threads; block tile 64 rows x 64 feats x 128 K;
// thread 4x4; packed f32x2; next chunk register-prefetched during compute.
// ---------------------------------------------------------------------------
#define HS 68
__global__ void __launch_bounds__(256) wh_main(const float* __restrict__ h,
                                               const float* __restrict__ W) {
    __shared__ __align__(16) float Wc[64 * 64];   // Wc[k][f]    16 KB
    __shared__ __align__(16) float hT[64 * HS];   // hT[k][row]  17.4 KB

    const int t  = threadIdx.x;
    const int tx = t & 15;       // feats tx*4 .. +3
    const int ty = t >> 4;       // rows  ty*4 .. +3
    const int r0 = blockIdx.x * 64;
    const int kbase = blockIdx.y * 128;   // K-quarter origin

    float4 wr[4], hr[4];
#pragma unroll
    for (int i = 0; i < 4; i++) {        // prologue: chunk 0 into regs
        int idx = t + i * 256;
        wr[i] = ((const float4*)W)[(size_t)(kbase + (idx >> 4)) * 16 + (idx & 15)];
        hr[i] = ((const float4*)h)[(size_t)(r0 + (idx & 63)) * (IN_F / 4)
                                   + (kbase >> 2) + (idx >> 6)];
    }

    unsigned long long acc[4][2];
#pragma unroll
    for (int r = 0; r < 4; r++) { acc[r][0] = 0ull; acc[r][1] = 0ull; }

#pragma unroll
    for (int c = 0; c < 2; c++) {
        __syncthreads();                  // previous chunk's reads done
#pragma unroll
        for (int i = 0; i < 4; i++) {     // stage regs -> smem
            int idx = t + i * 256;
            ((float4*)Wc)[idx] = wr[i];
            int row = idx & 63, kq = idx >> 6;
            hT[(kq * 4 + 0) * HS + row] = hr[i].x;
            hT[(kq * 4 + 1) * HS + row] = hr[i].y;
            hT[(kq * 4 + 2) * HS + row] = hr[i].z;
            hT[(kq * 4 + 3) * HS + row] = hr[i].w;
        }
        __syncthreads();
        if (c < 1) {                      // prefetch next chunk into regs
#pragma unroll
            for (int i = 0; i < 4; i++) {
                int idx = t + i * 256;
                wr[i] = ((const float4*)W)[(size_t)(kbase + 64 + (idx >> 4)) * 16
                                           + (idx & 15)];
                hr[i] = ((const float4*)h)[(size_t)(r0 + (idx & 63)) * (IN_F / 4)
                                           + (kbase >> 2) + 16 + (idx >> 6)];
            }
        }
#pragma unroll 4
        for (int k = 0; k < 64; k++) {
            ulonglong2 w = *(const ulonglong2*)&Wc[k * 64 + tx * 4];
            float4 hv = *(const float4*)&hT[k * HS + ty * 4];
            unsigned long long hd;
            asm("mov.b64 %0, {%1, %1};" : "=l"(hd) : "f"(hv.x));
            asm("fma.rn.f32x2 %0, %1, %2, %0;" : "+l"(acc[0][0]) : "l"(hd), "l"(w.x));
            asm("fma.rn.f32x2 %0, %1, %2, %0;" : "+l"(acc[0][1]) : "l"(hd), "l"(w.y));
            asm("mov.b64 %0, {%1, %1};" : "=l"(hd) : "f"(hv.y));
            asm("fma.rn.f32x2 %0, %1, %2, %0;" : "+l"(acc[1][0]) : "l"(hd), "l"(w.x));
            asm("fma.rn.f32x2 %0, %1, %2, %0;" : "+l"(acc[1][1]) : "l"(hd), "l"(w.y));
            asm("mov.b64 %0, {%1, %1};" : "=l"(hd) : "f"(hv.z));
            asm("fma.rn.f32x2 %0, %1, %2, %0;" : "+l"(acc[2][0]) : "l"(hd), "l"(w.x));
            asm("fma.rn.f32x2 %0, %1, %2, %0;" : "+l"(acc[2][1]) : "l"(hd), "l"(w.y));
            asm("mov.b64 %0, {%1, %1};" : "=l"(hd) : "f"(hv.w));
            asm("fma.rn.f32x2 %0, %1, %2, %0;" : "+l"(acc[3][0]) : "l"(hd), "l"(w.x));
            asm("fma.rn.f32x2 %0, %1, %2, %0;" : "+l"(acc[3][1]) : "l"(hd), "l"(w.y));
        }
    }

    float* dst = g_WHp + (size_t)blockIdx.y * (N * OUT_F);
#pragma unroll
    for (int r = 0; r < 4; r++) {
        float v0, v1, v2, v3;
        asm("mov.b64 {%0, %1}, %2;" : "=f"(v0), "=f"(v1) : "l"(acc[r][0]));
        asm("mov.b64 {%0, %1}, %2;" : "=f"(v2), "=f"(v3) : "l"(acc[r][1]));
        *(float4*)(dst + (size_t)(r0 + ty * 4 + r) * OUT_F + tx * 4) =
            make_float4(v0, v1, v2, v3);
    }
}

// ---------------------------------------------------------------------------
// Kernel A2: wh_epi — combine K-quarters, emit half-transposed WH, attn dots,
// wh2 max. grid 512 x 256 (16 rows/block).
// ---------------------------------------------------------------------------
__global__ void __launch_bounds__(256) wh_epi(const float* __restrict__ a) {
    __shared__ float a1s[64], a2s[64];
    __shared__ float red1[16 * 17], red2[16 * 17];
    __shared__ __half hs[64 * 18];

    const int t   = threadIdx.x;
    const int fq  = t & 15;      // feats fq*4 .. +3
    const int row = t >> 4;      // 0..15
    const int r0  = blockIdx.x * 16;

    if (t < 64) { a1s[t] = a[t]; a2s[t] = a[OUT_F + t]; }

    const size_t idx = (size_t)(r0 + row) * 16 + fq;
    float v0 = 0.f, v1 = 0.f, v2 = 0.f, v3 = 0.f;
#pragma unroll
    for (int q = 0; q < KSPL; q++) {
        float4 va = ((const float4*)g_WHp)[(size_t)q * (N * 16) + idx];
        v0 += va.x; v1 += va.y; v2 += va.z; v3 += va.w;
    }

    hs[(fq * 4 + 0) * 18 + row] = __float2half(v0);
    hs[(fq * 4 + 1) * 18 + row] = __float2half(v1);
    hs[(fq * 4 + 2) * 18 + row] = __float2half(v2);
    hs[(fq * 4 + 3) * 18 + row] = __float2half(v3);
    __syncthreads();   // a1s/a2s visible

    float p1 = v0 * a1s[fq * 4] + v1 * a1s[fq * 4 + 1]
             + v2 * a1s[fq * 4 + 2] + v3 * a1s[fq * 4 + 3];
    float p2 = v0 * a2s[fq * 4] + v1 * a2s[fq * 4 + 1]
             + v2 * a2s[fq * 4 + 2] + v3 * a2s[fq * 4 + 3];
    red1[row * 17 + fq] = p1;
    red2[row * 17 + fq] = p2;
    __syncthreads();

    if (t < 64) {   // transposed half store: 32B per feature
        uint32_t u[8];
#pragma unroll
        for (int q = 0; q < 8; q++) u[q] = *(const uint32_t*)&hs[t * 18 + q * 2];
        uint4* dst = (uint4*)(g_WHth + (size_t)t * N + r0);
        dst[0] = make_uint4(u[0], u[1], u[2], u[3]);
        dst[1] = make_uint4(u[4], u[5], u[6], u[7]);
    }
    if (t < 16) {
        float d1 = 0.f, d2 = 0.f;
#pragma unroll
        for (int q = 0; q < 16; q++) { d1 += red1[t * 17 + q]; d2 += red2[t * 17 + q]; }
        d1 *= LOG2E; d2 *= LOG2E;
        g_wh1[r0 + t] = d1;
        g_wh2[r0 + t] = d2;
        float m = d2;
#pragma unroll
        for (int off = 8; off > 0; off >>= 1)
            m = fmaxf(m, __shfl_xor_sync(0x0000FFFFu, m, off));
        if (t == 0) atomicMax(&g_m2u, f2key(m));   // idempotent across replays
    }
}

// ---------------------------------------------------------------------------
// Kernel C: scores (exp2 in half2, per-row shift, mask folded into shift)
//  -> PV matmul (f16 m16n8k16); row sums via ones-column mma (ch==0 warps).
//  grid (N/TI, SPLIT) = (128, 16). adjacency + V + wh2 via cp.async double buf.
// ---------------------------------------------------------------------------
__global__ void __launch_bounds__(256, 3) gat_kernel(const int* __restrict__ adj) {
    extern __shared__ __align__(16) char sm[];
    int*      adjs = (int*)(sm + ADJ_OFF);
    uint32_t* Vs   = (uint32_t*)(sm + VS_OFF);
    uint32_t* Ps   = (uint32_t*)(sm + PS_OFF);
    float*    wh2s = (float*)(sm + WH2_OFF);
    float*    wh1s = (float*)(sm + WH1_OFF);
    float*    shs  = (float*)(sm + SHS_OFF);

    const int t    = threadIdx.x;
    const int ry   = t >> 4;            // score rows: ry + 16k
    const int tx   = t & 15;
    const int jb   = tx * 4;            // score cols within tile
    const int lane = t & 31;
    const int warp = t >> 5;
    const int gid  = lane >> 2;
    const int tid  = lane & 3;
    const int rs   = (warp >> 1) * 16;  // mma row stripe
    const int ch   = (warp & 1) * 32;   // mma col half
    const int i0   = blockIdx.x * TI;
    const int sp   = blockIdx.y;
    const int jbase = sp * JSPAN;

    const float m2L = key2f(g_m2u);
    if (t < TI) {
        float w1 = g_wh1[i0 + t];
        wh1s[t] = w1;
        float sh = w1 + m2L;
        shs[t] = (sh > 0.f) ? sh : NEG_SLOPE * sh;   // row max in log2 domain
    }

    // prologue group: adj(0), Vs(0), wh2(0)
#pragma unroll
    for (int i = 0; i < 4; i++) {
        int idx = t + i * 256;
        int row = idx >> 4, cc = idx & 15;
        CP_ASYNC16(su(sm + ADJ_OFF) + row * 256 + cc * 16,
                   (const void*)(adj + (size_t)(i0 + row) * N + jbase + cc * 4));
    }
#pragma unroll
    for (int i = 0; i < 2; i++) {
        int idx = t + i * 256;
        int f = idx >> 3, cc = idx & 7;
        CP_ASYNC16(su(sm + VS_OFF) + f * 144 + cc * 16,
                   (const void*)(g_WHth + (size_t)f * N + jbase + cc * 8));
    }
    if (t < 16) CP_ASYNC16(su(wh2s) + t * 16, (const void*)(g_wh2 + jbase + t * 4));
    CP_COMMIT();

    // init ones/zero rows (64..71) of both V buffers (cp only writes rows 0..63)
    for (int w = t; w < 2 * 8 * VSW; w += 256) {
        int buf = w / (8 * VSW);
        int rem = w % (8 * VSW);
        int rr  = 64 + rem / VSW;
        Vs[buf * VBUF + rr * VSW + rem % VSW] = (rr == 64) ? 0x3C003C00u : 0u;
    }

    __syncthreads();   // wh1s/shs + ones rows visible
    float b1r[4], mshr[4];
#pragma unroll
    for (int k = 0; k < 4; k++) {
        b1r[k]  = wh1s[ry + 16 * k];
        mshr[k] = -shs[ry + 16 * k];
    }

    float c[4][4], csum[4];
#pragma unroll
    for (int nt = 0; nt < 4; nt++)
#pragma unroll
        for (int q = 0; q < 4; q++) c[nt][q] = 0.f;
#pragma unroll
    for (int q = 0; q < 4; q++) csum[q] = 0.f;

    for (int tt = 0; tt < NT_S; ++tt) {
        const int b = tt & 1;
        CP_WAIT0();
        __syncthreads();   // cp(tt) visible to all; mma(tt-1) complete

        // ---- issue cp for tile tt+1 into b^1 buffers (safe after sync) ----
        if (tt + 1 < NT_S) {
            const int jn = jbase + (tt + 1) * TJ;
            const int bo = (b ^ 1);
#pragma unroll
            for (int i = 0; i < 4; i++) {
                int idx = t + i * 256;
                int row = idx >> 4, cc = idx & 15;
                CP_ASYNC16(su(sm + ADJ_OFF) + bo * 16384 + row * 256 + cc * 16,
                           (const void*)(adj + (size_t)(i0 + row) * N + jn + cc * 4));
            }
#pragma unroll
            for (int i = 0; i < 2; i++) {
                int idx = t + i * 256;
                int f = idx >> 3, cc = idx & 7;
                CP_ASYNC16(su(sm + VS_OFF) + bo * 10368 + f * 144 + cc * 16,
                           (const void*)(g_WHth + (size_t)f * N + jn + cc * 8));
            }
            if (t < 16) CP_ASYNC16(su(wh2s) + bo * 256 + t * 16,
                                   (const void*)(g_wh2 + jn + t * 4));
        }
        CP_COMMIT();

        // ---- scores: e in fp32, mask via shift-select, exp in half2 ----
        const float4 w2 = *(const float4*)&wh2s[b * 64 + jb];
        const int* ab = adjs + b * 4096;
#pragma unroll
        for (int k = 0; k < 4; k++) {
            const int r = ry + 16 * k;
            const int4 av = *(const int4*)(ab + r * 64 + jb);
            const float b1 = b1r[k];
            const float ms = mshr[k];
            const float mB = ms - 1024.0f;   // masked: exp2 underflows to 0 in half
            float x0 = b1 + w2.x; x0 = fmaxf(x0, NEG_SLOPE * x0) + ((av.x > 0) ? ms : mB);
            float x1 = b1 + w2.y; x1 = fmaxf(x1, NEG_SLOPE * x1) + ((av.y > 0) ? ms : mB);
            float x2 = b1 + w2.z; x2 = fmaxf(x2, NEG_SLOPE * x2) + ((av.z > 0) ? ms : mB);
            float x3 = b1 + w2.w; x3 = fmaxf(x3, NEG_SLOPE * x3) + ((av.w > 0) ? ms : mB);
            uint32_t e01 = h2u(__floats2half2_rn(x0, x1));
            uint32_t e23 = h2u(__floats2half2_rn(x2, x3));
            uint32_t p01, p23;
            asm("ex2.approx.f16x2 %0, %1;" : "=r"(p01) : "r"(e01));
            asm("ex2.approx.f16x2 %0, %1;" : "=r"(p23) : "r"(e23));
            *(uint2*)&Ps[r * PSW + tx * 2] = make_uint2(p01, p23);
        }
        __syncthreads();   // Ps complete

        // ---- tensor-core PV: per warp 16x32 output + ones-column row sums ----
        const uint32_t* vb = Vs + b * VBUF;
#pragma unroll
        for (int kc = 0; kc < 4; kc++) {
            const int k0 = kc * 8;
            uint32_t a0 = Ps[(rs + gid) * PSW + k0 + tid];
            uint32_t a1 = Ps[(rs + gid + 8) * PSW + k0 + tid];
            uint32_t a2 = Ps[(rs + gid) * PSW + k0 + tid + 4];
            uint32_t a3 = Ps[(rs + gid + 8) * PSW + k0 + tid + 4];
#pragma unroll
            for (int nt = 0; nt < 4; nt++) {
                const int n = ch + nt * 8 + gid;
                uint32_t b0 = vb[n * VSW + k0 + tid];
                uint32_t b1v = vb[n * VSW + k0 + tid + 4];
                mma_f16(c[nt], a0, a1, a2, a3, b0, b1v);
            }
            if (ch == 0) {   // ones-column: row sums in fp32 accumulator
                uint32_t b0 = vb[(64 + gid) * VSW + k0 + tid];
                uint32_t b1v = vb[(64 + gid) * VSW + k0 + tid + 4];
                mma_f16(csum, a0, a1, a2, a3, b0, b1v);
            }
        }
    }

    // ---- row sums from ones-column accumulators ----
    if (ch == 0 && tid == 0) {
        g_psum[sp * N + i0 + rs + gid]     = csum[0];
        g_psum[sp * N + i0 + rs + gid + 8] = csum[2];
    }

    // ---- store unnormalized partials (half2) ----
#pragma unroll
    for (int nt = 0; nt < 4; nt++) {
        const int col = ch + nt * 8 + 2 * tid;
        const int row0 = i0 + rs + gid;
        *(uint32_t*)&g_pacc[((size_t)sp * N + row0) * OUT_F + col] =
            h2u(__floats2half2_rn(c[nt][0], c[nt][1]));
        *(uint32_t*)&g_pacc[((size_t)sp * N + row0 + 8) * OUT_F + col] =
            h2u(__floats2half2_rn(c[nt][2], c[nt][3]));
    }
}

// ---------------------------------------------------------------------------
// Kernel D: combine partials (half2 -> fp32), normalize, elu
// ---------------------------------------------------------------------------
__global__ void __launch_bounds__(256) combine_kernel(float* __restrict__ out) {
    const int idx = blockIdx.x * 256 + threadIdx.x;   // N*16 slots of 4 cols
    const int r = idx >> 4;

    float4 a = make_float4(0.f, 0.f, 0.f, 0.f);
    float s = 0.f;
#pragma unroll
    for (int sp = 0; sp < SPLIT; sp++) {
        uint2 p = ((const uint2*)g_pacc)[(size_t)sp * (N * 16) + idx];
        float2 f01 = __half22float2(*(const __half2*)&p.x);
        float2 f23 = __half22float2(*(const __half2*)&p.y);
        a.x += f01.x; a.y += f01.y; a.z += f23.x; a.w += f23.y;
        s += g_psum[sp * N + r];
    }
    const float inv = 1.f / s;
    float v;
    float4 o;
    v = a.x * inv; o.x = (v > 0.f) ? v : expm1f(v);
    v = a.y * inv; o.y = (v > 0.f) ? v : expm1f(v);
    v = a.z * inv; o.z = (v > 0.f) ? v : expm1f(v);
    v = a.w * inv; o.w = (v > 0.f) ? v : expm1f(v);
    ((float4*)out)[idx] = o;
}

// ---------------------------------------------------------------------------
extern "C" void kernel_launch(void* const* d_in, const int* in_sizes, int n_in,
                              void* d_out, int out_size) {
    const float* h   = nullptr;
    const int*   adj = nullptr;
    const float* W   = nullptr;
    const float* a   = nullptr;
    for (int i = 0; i < n_in; i++) {
        long long sz = in_sizes[i];
        if (sz == (long long)N * IN_F)          h   = (const float*)d_in[i];
        else if (sz == (long long)N * N)        adj = (const int*)d_in[i];
        else if (sz == (long long)IN_F * OUT_F) W   = (const float*)d_in[i];
        else if (sz == 2 * OUT_F)               a   = (const float*)d_in[i];
    }

    cudaFuncSetAttribute(gat_kernel, cudaFuncAttributeMaxDynamicSharedMemorySize, GAT_SMEM);

    wh_main<<<dim3(128, KSPL), 256>>>(h, W);
    wh_epi<<<512, 256>>>(a);
    gat_kernel<<<dim3(N / TI, SPLIT), 256, GAT_SMEM>>>(adj);
    combine_kernel<<<(N * 16) / 256, 256>>>((float*)d_out);
}

// round 15
// speedup vs baseline: 1.4797x; 1.0215x over previous
#include <cuda_runtime.h>
#include <cuda_fp16.h>
#include <cstdint>

#define N 8192
#define IN_F 512
#define OUT_F 64
#define NEG_SLOPE 0.01f
#define LOG2E 1.44269504088896340736f

#define TI 64
#define TJ 64
#define SPLIT 8
#define JSPAN (N / SPLIT)     // 1024
#define NT_S (JSPAN / TJ)     // 16

#define PSW 36   // Ps row stride (u32): frag banks conflict-free
#define VSW 36   // Vs row stride (u32)
#define VBUF (72 * VSW)       // V buffer stride (u32): 64 data rows + 8 ones/zero rows

// gat dynamic smem layout (bytes)
#define ADJ_OFF 0              // 2 x 16384 (adjacency tiles, 64x64 int)
#define VS_OFF  32768          // 2 x 10368 (V tiles + ones rows, half2, n-major)
#define PS_OFF  53504          // 9216      (P tile, half2)
#define WH2_OFF 62720          // 2 x 256
#define WH1_OFF 63232          // 256
#define SHS_OFF 63488          // 256
#define GAT_SMEM 63744

// Scratch (allocation-free rule: device globals)
#define KSPL 4
__device__ __align__(16) float g_WHp[KSPL * N * OUT_F];   // K-split partials (8 MB)
__device__ __align__(16) __half g_WHth[OUT_F * N];        // WH transposed, half
__device__ float g_wh1[N];           // pre-scaled by LOG2E
__device__ float g_wh2[N];           // pre-scaled by LOG2E
__device__ unsigned g_m2u = 0;       // order-preserving-key max of wh2L
__device__ __align__(16) __half g_pacc[SPLIT * N * OUT_F];  // 8 MB partial PV (half)
__device__ __align__(16) float g_psum[N * SPLIT];           // row sums, [row][sp]

__device__ __forceinline__ uint32_t su(const void* p) {
    return (uint32_t)__cvta_generic_to_shared(p);
}
#define CP_ASYNC16(dst, src) \
    asm volatile("cp.async.cg.shared.global [%0], [%1], 16;" :: "r"(dst), "l"(src))
#define CP_COMMIT() asm volatile("cp.async.commit_group;" ::: "memory")
#define CP_WAIT0()  asm volatile("cp.async.wait_group 0;" ::: "memory")

// order-preserving float<->unsigned key
__device__ __forceinline__ unsigned f2key(float x) {
    unsigned b = __float_as_uint(x);
    return (b & 0x80000000u) ? ~b : (b | 0x80000000u);
}
__device__ __forceinline__ float key2f(unsigned u) {
    return __uint_as_float((u & 0x80000000u) ? (u & 0x7FFFFFFFu) : ~u);
}
__device__ __forceinline__ uint32_t h2u(__half2 h) { return *(uint32_t*)&h; }

// f16 m16n8k16 tensor-core mma, f32 accumulate (baseline PTX, sm_103 ok)
__device__ __forceinline__ void mma_f16(float* c, uint32_t a0, uint32_t a1,
                                        uint32_t a2, uint32_t a3,
                                        uint32_t b0, uint32_t b1) {
    asm volatile(
        "mma.sync.aligned.m16n8k16.row.col.f32.f16.f16.f32 "
        "{%0,%1,%2,%3}, {%4,%5,%6,%7}, {%8,%9}, {%0,%1,%2,%3};"
        : "+f"(c[0]), "+f"(c[1]), "+f"(c[2]), "+f"(c[3])
        : "r"(a0), "r"(a1), "r"(a2), "r"(a3), "r"(b0), "r"(b1));
}

// ---------------------------------------------------------------------------
// Kernel A1: wh_main — partial WH over a K-quarter.
// grid (128, 4) x 256 threads; block tile 64 rows x 64 feats x 128 K;
// thread 4x4; packed f32x2; next chunk register-prefetched during compute.
// ---------------------------------------------------------------------------
#define HS 68
__global__ void __launch_bounds__(256) wh_main(const float* __restrict__ h,
                                               const float* __restrict__ W) {
    __shared__ __align__(16) float Wc[64 * 64];   // Wc[k][f]    16 KB
    __shared__ __align__(16) float hT[64 * HS];   // hT[k][row]  17.4 KB

    const int t  = threadIdx.x;
    const int tx = t & 15;       // feats tx*4 .. +3
    const int ty = t >> 4;       // rows  ty*4 .. +3
    const int r0 = blockIdx.x * 64;
    const int kbase = blockIdx.y * 128;   // K-quarter origin

    float4 wr[4], hr[4];
#pragma unroll
    for (int i = 0; i < 4; i++) {        // prologue: chunk 0 into regs
        int idx = t + i * 256;
        wr[i] = ((const float4*)W)[(size_t)(kbase + (idx >> 4)) * 16 + (idx & 15)];
        hr[i] = ((const float4*)h)[(size_t)(r0 + (idx & 63)) * (IN_F / 4)
                                   + (kbase >> 2) + (idx >> 6)];
    }

    unsigned long long acc[4][2];
#pragma unroll
    for (int r = 0; r < 4; r++) { acc[r][0] = 0ull; acc[r][1] = 0ull; }

#pragma unroll
    for (int c = 0; c < 2; c++) {
        __syncthreads();                  // previous chunk's reads done
#pragma unroll
        for (int i = 0; i < 4; i++) {     // stage regs -> smem
            int idx = t + i * 256;
            ((float4*)Wc)[idx] = wr[i];
            int row = idx & 63, kq = idx >> 6;
            hT[(kq * 4 + 0) * HS + row] = hr[i].x;
            hT[(kq * 4 + 1) * HS + row] = hr[i].y;
            hT[(kq * 4 + 2) * HS + row] = hr[i].z;
            hT[(kq * 4 + 3) * HS + row] = hr[i].w;
        }
        __syncthreads();
        if (c < 1) {                      // prefetch next chunk into regs
#pragma unroll
            for (int i = 0; i < 4; i++) {
                int idx = t + i * 256;
                wr[i] = ((const float4*)W)[(size_t)(kbase + 64 + (idx >> 4)) * 16
                                           + (idx & 15)];
                hr[i] = ((const float4*)h)[(size_t)(r0 + (idx & 63)) * (IN_F / 4)
                                           + (kbase >> 2) + 16 + (idx >> 6)];
            }
        }
#pragma unroll 4
        for (int k = 0; k < 64; k++) {
            ulonglong2 w = *(const ulonglong2*)&Wc[k * 64 + tx * 4];
            float4 hv = *(const float4*)&hT[k * HS + ty * 4];
            unsigned long long hd;
            asm("mov.b64 %0, {%1, %1};" : "=l"(hd) : "f"(hv.x));
            asm("fma.rn.f32x2 %0, %1, %2, %0;" : "+l"(acc[0][0]) : "l"(hd), "l"(w.x));
            asm("fma.rn.f32x2 %0, %1, %2, %0;" : "+l"(acc[0][1]) : "l"(hd), "l"(w.y));
            asm("mov.b64 %0, {%1, %1};" : "=l"(hd) : "f"(hv.y));
            asm("fma.rn.f32x2 %0, %1, %2, %0;" : "+l"(acc[1][0]) : "l"(hd), "l"(w.x));
            asm("fma.rn.f32x2 %0, %1, %2, %0;" : "+l"(acc[1][1]) : "l"(hd), "l"(w.y));
            asm("mov.b64 %0, {%1, %1};" : "=l"(hd) : "f"(hv.z));
            asm("fma.rn.f32x2 %0, %1, %2, %0;" : "+l"(acc[2][0]) : "l"(hd), "l"(w.x));
            asm("fma.rn.f32x2 %0, %1, %2, %0;" : "+l"(acc[2][1]) : "l"(hd), "l"(w.y));
            asm("mov.b64 %0, {%1, %1};" : "=l"(hd) : "f"(hv.w));
            asm("fma.rn.f32x2 %0, %1, %2, %0;" : "+l"(acc[3][0]) : "l"(hd), "l"(w.x));
            asm("fma.rn.f32x2 %0, %1, %2, %0;" : "+l"(acc[3][1]) : "l"(hd), "l"(w.y));
        }
    }

    float* dst = g_WHp + (size_t)blockIdx.y * (N * OUT_F);
#pragma unroll
    for (int r = 0; r < 4; r++) {
        float v0, v1, v2, v3;
        asm("mov.b64 {%0, %1}, %2;" : "=f"(v0), "=f"(v1) : "l"(acc[r][0]));
        asm("mov.b64 {%0, %1}, %2;" : "=f"(v2), "=f"(v3) : "l"(acc[r][1]));
        *(float4*)(dst + (size_t)(r0 + ty * 4 + r) * OUT_F + tx * 4) =
            make_float4(v0, v1, v2, v3);
    }
}

// ---------------------------------------------------------------------------
// Kernel A2: wh_epi — combine K-quarters, emit half-transposed WH, attn dots,
// wh2 max. grid 512 x 256 (16 rows/block).
// ---------------------------------------------------------------------------
__global__ void __launch_bounds__(256) wh_epi(const float* __restrict__ a) {
    __shared__ float a1s[64], a2s[64];
    __shared__ float red1[16 * 17], red2[16 * 17];
    __shared__ __half hs[64 * 18];

    const int t   = threadIdx.x;
    const int fq  = t & 15;      // feats fq*4 .. +3
    const int row = t >> 4;      // 0..15
    const int r0  = blockIdx.x * 16;

    if (t < 64) { a1s[t] = a[t]; a2s[t] = a[OUT_F + t]; }

    const size_t idx = (size_t)(r0 + row) * 16 + fq;
    float v0 = 0.f, v1 = 0.f, v2 = 0.f, v3 = 0.f;
#pragma unroll
    for (int q = 0; q < KSPL; q++) {
        float4 va = ((const float4*)g_WHp)[(size_t)q * (N * 16) + idx];
        v0 += va.x; v1 += va.y; v2 += va.z; v3 += va.w;
    }

    hs[(fq * 4 + 0) * 18 + row] = __float2half(v0);
    hs[(fq * 4 + 1) * 18 + row] = __float2half(v1);
    hs[(fq * 4 + 2) * 18 + row] = __float2half(v2);
    hs[(fq * 4 + 3) * 18 + row] = __float2half(v3);
    __syncthreads();   // a1s/a2s visible

    float p1 = v0 * a1s[fq * 4] + v1 * a1s[fq * 4 + 1]
             + v2 * a1s[fq * 4 + 2] + v3 * a1s[fq * 4 + 3];
    float p2 = v0 * a2s[fq * 4] + v1 * a2s[fq * 4 + 1]
             + v2 * a2s[fq * 4 + 2] + v3 * a2s[fq * 4 + 3];
    red1[row * 17 + fq] = p1;
    red2[row * 17 + fq] = p2;
    __syncthreads();

    if (t < 64) {   // transposed half store: 32B per feature
        uint32_t u[8];
#pragma unroll
        for (int q = 0; q < 8; q++) u[q] = *(const uint32_t*)&hs[t * 18 + q * 2];
        uint4* dst = (uint4*)(g_WHth + (size_t)t * N + r0);
        dst[0] = make_uint4(u[0], u[1], u[2], u[3]);
        dst[1] = make_uint4(u[4], u[5], u[6], u[7]);
    }
    if (t < 16) {
        float d1 = 0.f, d2 = 0.f;
#pragma unroll
        for (int q = 0; q < 16; q++) { d1 += red1[t * 17 + q]; d2 += red2[t * 17 + q]; }
        d1 *= LOG2E; d2 *= LOG2E;
        g_wh1[r0 + t] = d1;
        g_wh2[r0 + t] = d2;
        float m = d2;
#pragma unroll
        for (int off = 8; off > 0; off >>= 1)
            m = fmaxf(m, __shfl_xor_sync(0x0000FFFFu, m, off));
        if (t == 0) atomicMax(&g_m2u, f2key(m));   // idempotent across replays
    }
}

// ---------------------------------------------------------------------------
// Kernel C: scores (exp2 in half2, per-row shift, mask folded into shift)
//  -> PV matmul (f16 m16n8k16); row sums via ones-column mma (ch==0 warps).
//  grid (N/TI, SPLIT) = (128, 8). adjacency + V + wh2 via cp.async double buf.
// ---------------------------------------------------------------------------
__global__ void __launch_bounds__(256, 3) gat_kernel(const int* __restrict__ adj) {
    extern __shared__ __align__(16) char sm[];
    int*      adjs = (int*)(sm + ADJ_OFF);
    uint32_t* Vs   = (uint32_t*)(sm + VS_OFF);
    uint32_t* Ps   = (uint32_t*)(sm + PS_OFF);
    float*    wh2s = (float*)(sm + WH2_OFF);
    float*    wh1s = (float*)(sm + WH1_OFF);
    float*    shs  = (float*)(sm + SHS_OFF);

    const int t    = threadIdx.x;
    const int ry   = t >> 4;            // score rows: ry + 16k
    const int tx   = t & 15;
    const int jb   = tx * 4;            // score cols within tile
    const int lane = t & 31;
    const int warp = t >> 5;
    const int gid  = lane >> 2;
    const int tid  = lane & 3;
    const int rs   = (warp >> 1) * 16;  // mma row stripe
    const int ch   = (warp & 1) * 32;   // mma col half
    const int i0   = blockIdx.x * TI;
    const int sp   = blockIdx.y;
    const int jbase = sp * JSPAN;

    const float m2L = key2f(g_m2u);
    if (t < TI) {
        float w1 = g_wh1[i0 + t];
        wh1s[t] = w1;
        float sh = w1 + m2L;
        shs[t] = (sh > 0.f) ? sh : NEG_SLOPE * sh;   // row max in log2 domain
    }

    // prologue group: adj(0), Vs(0), wh2(0)
#pragma unroll
    for (int i = 0; i < 4; i++) {
        int idx = t + i * 256;
        int row = idx >> 4, cc = idx & 15;
        CP_ASYNC16(su(sm + ADJ_OFF) + row * 256 + cc * 16,
                   (const void*)(adj + (size_t)(i0 + row) * N + jbase + cc * 4));
    }
#pragma unroll
    for (int i = 0; i < 2; i++) {
        int idx = t + i * 256;
        int f = idx >> 3, cc = idx & 7;
        CP_ASYNC16(su(sm + VS_OFF) + f * 144 + cc * 16,
                   (const void*)(g_WHth + (size_t)f * N + jbase + cc * 8));
    }
    if (t < 16) CP_ASYNC16(su(wh2s) + t * 16, (const void*)(g_wh2 + jbase + t * 4));
    CP_COMMIT();

    // init ones/zero rows (64..71) of both V buffers (cp only writes rows 0..63)
    for (int w = t; w < 2 * 8 * VSW; w += 256) {
        int buf = w / (8 * VSW);
        int rem = w % (8 * VSW);
        int rr  = 64 + rem / VSW;
        Vs[buf * VBUF + rr * VSW + rem % VSW] = (rr == 64) ? 0x3C003C00u : 0u;
    }

    __syncthreads();   // wh1s/shs + ones rows visible
    float b1r[4], mshr[4];
#pragma unroll
    for (int k = 0; k < 4; k++) {
        b1r[k]  = wh1s[ry + 16 * k];
        mshr[k] = -shs[ry + 16 * k];
    }

    float c[4][4], csum[4];
#pragma unroll
    for (int nt = 0; nt < 4; nt++)
#pragma unroll
        for (int q = 0; q < 4; q++) c[nt][q] = 0.f;
#pragma unroll
    for (int q = 0; q < 4; q++) csum[q] = 0.f;

    for (int tt = 0; tt < NT_S; ++tt) {
        const int b = tt & 1;
        CP_WAIT0();
        __syncthreads();   // cp(tt) visible to all; mma(tt-1) complete

        // ---- issue cp for tile tt+1 into b^1 buffers (safe after sync) ----
        if (tt + 1 < NT_S) {
            const int jn = jbase + (tt + 1) * TJ;
            const int bo = (b ^ 1);
#pragma unroll
            for (int i = 0; i < 4; i++) {
                int idx = t + i * 256;
                int row = idx >> 4, cc = idx & 15;
                CP_ASYNC16(su(sm + ADJ_OFF) + bo * 16384 + row * 256 + cc * 16,
                           (const void*)(adj + (size_t)(i0 + row) * N + jn + cc * 4));
            }
#pragma unroll
            for (int i = 0; i < 2; i++) {
                int idx = t + i * 256;
                int f = idx >> 3, cc = idx & 7;
                CP_ASYNC16(su(sm + VS_OFF) + bo * 10368 + f * 144 + cc * 16,
                           (const void*)(g_WHth + (size_t)f * N + jn + cc * 8));
            }
            if (t < 16) CP_ASYNC16(su(wh2s) + bo * 256 + t * 16,
                                   (const void*)(g_wh2 + jn + t * 4));
        }
        CP_COMMIT();

        // ---- scores: e in fp32, mask via shift-select, exp in half2 ----
        const float4 w2 = *(const float4*)&wh2s[b * 64 + jb];
        const int* ab = adjs + b * 4096;
#pragma unroll
        for (int k = 0; k < 4; k++) {
            const int r = ry + 16 * k;
            const int4 av = *(const int4*)(ab + r * 64 + jb);
            const float b1 = b1r[k];
            const float ms = mshr[k];
            const float mB = ms - 1024.0f;   // masked: exp2 underflows to 0 in half
            float x0 = b1 + w2.x; x0 = fmaxf(x0, NEG_SLOPE * x0) + ((av.x > 0) ? ms : mB);
            float x1 = b1 + w2.y; x1 = fmaxf(x1, NEG_SLOPE * x1) + ((av.y > 0) ? ms : mB);
            float x2 = b1 + w2.z; x2 = fmaxf(x2, NEG_SLOPE * x2) + ((av.z > 0) ? ms : mB);
            float x3 = b1 + w2.w; x3 = fmaxf(x3, NEG_SLOPE * x3) + ((av.w > 0) ? ms : mB);
            uint32_t e01 = h2u(__floats2half2_rn(x0, x1));
            uint32_t e23 = h2u(__floats2half2_rn(x2, x3));
            uint32_t p01, p23;
            asm("ex2.approx.f16x2 %0, %1;" : "=r"(p01) : "r"(e01));
            asm("ex2.approx.f16x2 %0, %1;" : "=r"(p23) : "r"(e23));
            *(uint2*)&Ps[r * PSW + tx * 2] = make_uint2(p01, p23);
        }
        __syncthreads();   // Ps complete

        // ---- tensor-core PV: per warp 16x32 output + ones-column row sums ----
        const uint32_t* vb = Vs + b * VBUF;
#pragma unroll
        for (int kc = 0; kc < 4; kc++) {
            const int k0 = kc * 8;
            uint32_t a0 = Ps[(rs + gid) * PSW + k0 + tid];
            uint32_t a1 = Ps[(rs + gid + 8) * PSW + k0 + tid];
            uint32_t a2 = Ps[(rs + gid) * PSW + k0 + tid + 4];
            uint32_t a3 = Ps[(rs + gid + 8) * PSW + k0 + tid + 4];
#pragma unroll
            for (int nt = 0; nt < 4; nt++) {
                const int n = ch + nt * 8 + gid;
                uint32_t b0 = vb[n * VSW + k0 + tid];
                uint32_t b1v = vb[n * VSW + k0 + tid + 4];
                mma_f16(c[nt], a0, a1, a2, a3, b0, b1v);
            }
            if (ch == 0) {   // ones-column: row sums in fp32 accumulator
                uint32_t b0 = vb[(64 + gid) * VSW + k0 + tid];
                uint32_t b1v = vb[(64 + gid) * VSW + k0 + tid + 4];
                mma_f16(csum, a0, a1, a2, a3, b0, b1v);
            }
        }
    }

    // ---- row sums from ones-column accumulators ([row][sp] layout) ----
    if (ch == 0 && tid == 0) {
        g_psum[(size_t)(i0 + rs + gid) * SPLIT + sp]     = csum[0];
        g_psum[(size_t)(i0 + rs + gid + 8) * SPLIT + sp] = csum[2];
    }

    // ---- store unnormalized partials (half2) ----
#pragma unroll
    for (int nt = 0; nt < 4; nt++) {
        const int col = ch + nt * 8 + 2 * tid;
        const int row0 = i0 + rs + gid;
        *(uint32_t*)&g_pacc[((size_t)sp * N + row0) * OUT_F + col] =
            h2u(__floats2half2_rn(c[nt][0], c[nt][1]));
        *(uint32_t*)&g_pacc[((size_t)sp * N + row0 + 8) * OUT_F + col] =
            h2u(__floats2half2_rn(c[nt][2], c[nt][3]));
    }
}

// ---------------------------------------------------------------------------
// Kernel D: combine partials (half2 -> fp32), normalize, elu
// ---------------------------------------------------------------------------
__global__ void __launch_bounds__(256) combine_kernel(float* __restrict__ out) {
    const int idx = blockIdx.x * 256 + threadIdx.x;   // N*16 slots of 4 cols
    const int r = idx >> 4;

    float4 a = make_float4(0.f, 0.f, 0.f, 0.f);
#pragma unroll
    for (int sp = 0; sp < SPLIT; sp++) {
        uint2 p = ((const uint2*)g_pacc)[(size_t)sp * (N * 16) + idx];
        float2 f01 = __half22float2(*(const __half2*)&p.x);
        float2 f23 = __half22float2(*(const __half2*)&p.y);
        a.x += f01.x; a.y += f01.y; a.z += f23.x; a.w += f23.y;
    }
    float4 s0 = *(const float4*)&g_psum[(size_t)r * SPLIT];
    float4 s1 = *(const float4*)&g_psum[(size_t)r * SPLIT + 4];
    float s = ((s0.x + s0.y) + (s0.z + s0.w)) + ((s1.x + s1.y) + (s1.z + s1.w));

    const float inv = 1.f / s;
    float v;
    float4 o;
    v = a.x * inv; o.x = (v > 0.f) ? v : expm1f(v);
    v = a.y * inv; o.y = (v > 0.f) ? v : expm1f(v);
    v = a.z * inv; o.z = (v > 0.f) ? v : expm1f(v);
    v = a.w * inv; o.w = (v > 0.f) ? v : expm1f(v);
    ((float4*)out)[idx] = o;
}

// ---------------------------------------------------------------------------
extern "C" void kernel_launch(void* const* d_in, const int* in_sizes, int n_in,
                              void* d_out, int out_size) {
    const float* h   = nullptr;
    const int*   adj = nullptr;
    const float* W   = nullptr;
    const float* a   = nullptr;
    for (int i = 0; i < n_in; i++) {
        long long sz = in_sizes[i];
        if (sz == (long long)N * IN_F)          h   = (const float*)d_in[i];
        else if (sz == (long long)N * N)        adj = (const int*)d_in[i];
        else if (sz == (long long)IN_F * OUT_F) W   = (const float*)d_in[i];
        else if (sz == 2 * OUT_F)               a   = (const float*)d_in[i];
    }

    cudaFuncSetAttribute(gat_kernel, cudaFuncAttributeMaxDynamicSharedMemorySize, GAT_SMEM);

    wh_main<<<dim3(128, KSPL), 256>>>(h, W);
    wh_epi<<<512, 256>>>(a);
    gat_kernel<<<dim3(N / TI, SPLIT), 256, GAT_SMEM>>>(adj);
    combine_kernel<<<(N * 16) / 256, 256>>>((float*)d_out);
}